// round 2
// baseline (speedup 1.0000x reference)
#include <cuda_runtime.h>

typedef unsigned long long ull;

#define NB    8
#define NC    512
#define NL    2048
#define NH    8
#define ND    64
#define NHID  512
#define NOQKV 1536

// Scratch (device globals — allocation-free per harness rules)
__device__ float g_qkv[(size_t)NB * NOQKV * NL];   // [b][1536][2048]
__device__ float g_att[(size_t)NB * NHID * NL];    // [b][512][2048]

// ---- packed f32x2 helpers (FFMA2 path; ptxas never auto-fuses this) ----
__device__ __forceinline__ ull f2pack(float x, float y) {
    ull u; asm("mov.b64 %0, {%1, %2};" : "=l"(u) : "f"(x), "f"(y)); return u;
}
__device__ __forceinline__ float2 f2unpack(ull u) {
    float2 f; asm("mov.b64 {%0, %1}, %2;" : "=f"(f.x), "=f"(f.y) : "l"(u)); return f;
}
__device__ __forceinline__ void ffma2(ull& d, ull a, ull b) {
    asm("fma.rn.f32x2 %0, %1, %2, %0;" : "+l"(d) : "l"(a), "l"(b));
}
__device__ __forceinline__ ull fmul2(ull a, ull b) {
    ull d; asm("mul.rn.f32x2 %0, %1, %2;" : "=l"(d) : "l"(a), "l"(b)); return d;
}

// ---------------------------------------------------------------------------
// Tiled fp32 GEMM:  Y[b][m][l] = sum_c W[m][c] * X[b][c][l]  (+ bias[m])
// 128x128 block tile, K-tile 16, 256 threads, 8x8 microtile, FFMA2 inner.
// A stored DUPLICATED in smem (float2{w,w}) so no pack instr in the hot loop.
// ---------------------------------------------------------------------------
template<int M, int K, bool HAS_BIAS>
__global__ __launch_bounds__(256) void gemm_kernel(
    const float* __restrict__ W, const float* __restrict__ X,
    const float* __restrict__ bias, float* __restrict__ Y)
{
    __shared__ float2 As2[16][132];   // [kk][m] duplicated
    __shared__ float  Bs [16][132];   // [kk][n]

    const int b  = blockIdx.z;
    const int m0 = blockIdx.y * 128;
    const int n0 = blockIdx.x * 128;
    const float* Xb = X + (size_t)b * K * NL;
    float*       Yb = Y + (size_t)b * M * NL;

    const int tid = threadIdx.x;
    const int tx  = tid & 15;      // n microtile (8 cols = 4 pairs)
    const int ty  = tid >> 4;      // m microtile (8 rows)

    const int am  = tid >> 1;          // 0..127
    const int akq = (tid & 1) * 8;     // 0 or 8
    const int bkk = tid >> 4;          // 0..15
    const int bnq = (tid & 15) * 8;    // 0..120

    ull acc[8][4];
    #pragma unroll
    for (int r = 0; r < 8; r++)
        #pragma unroll
        for (int c = 0; c < 4; c++) acc[r][c] = 0ULL;

    for (int k0 = 0; k0 < K; k0 += 16) {
        // A tile: 8 floats of one W row, written duplicated
        {
            const float* wp = &W[(size_t)(m0 + am) * K + k0 + akq];
            float4 w0 = *(const float4*)wp;
            float4 w1 = *(const float4*)(wp + 4);
            As2[akq + 0][am] = make_float2(w0.x, w0.x);
            As2[akq + 1][am] = make_float2(w0.y, w0.y);
            As2[akq + 2][am] = make_float2(w0.z, w0.z);
            As2[akq + 3][am] = make_float2(w0.w, w0.w);
            As2[akq + 4][am] = make_float2(w1.x, w1.x);
            As2[akq + 5][am] = make_float2(w1.y, w1.y);
            As2[akq + 6][am] = make_float2(w1.z, w1.z);
            As2[akq + 7][am] = make_float2(w1.w, w1.w);
        }
        // B tile: 8 floats, coalesced along l
        {
            const float* xp = &Xb[(size_t)(k0 + bkk) * NL + n0 + bnq];
            *(float4*)&Bs[bkk][bnq]     = *(const float4*)xp;
            *(float4*)&Bs[bkk][bnq + 4] = *(const float4*)(xp + 4);
        }
        __syncthreads();

        #pragma unroll
        for (int kk = 0; kk < 16; kk++) {
            ulonglong2 a0 = *(const ulonglong2*)&As2[kk][ty * 8];
            ulonglong2 a1 = *(const ulonglong2*)&As2[kk][ty * 8 + 2];
            ulonglong2 a2 = *(const ulonglong2*)&As2[kk][ty * 8 + 4];
            ulonglong2 a3 = *(const ulonglong2*)&As2[kk][ty * 8 + 6];
            ulonglong2 b0 = *(const ulonglong2*)&Bs[kk][tx * 8];
            ulonglong2 b1 = *(const ulonglong2*)&Bs[kk][tx * 8 + 4];
            ull av[8] = {a0.x, a0.y, a1.x, a1.y, a2.x, a2.y, a3.x, a3.y};
            ull bv[4] = {b0.x, b0.y, b1.x, b1.y};
            #pragma unroll
            for (int r = 0; r < 8; r++)
                #pragma unroll
                for (int c = 0; c < 4; c++)
                    ffma2(acc[r][c], av[r], bv[c]);
        }
        __syncthreads();
    }

    #pragma unroll
    for (int r = 0; r < 8; r++) {
        int m = m0 + ty * 8 + r;
        float bval = HAS_BIAS ? bias[m] : 0.0f;
        float2 c0 = f2unpack(acc[r][0]), c1 = f2unpack(acc[r][1]);
        float2 c2 = f2unpack(acc[r][2]), c3 = f2unpack(acc[r][3]);
        float4 o0 = make_float4(c0.x + bval, c0.y + bval, c1.x + bval, c1.y + bval);
        float4 o1 = make_float4(c2.x + bval, c2.y + bval, c3.x + bval, c3.y + bval);
        float* yp = &Yb[(size_t)m * NL + n0 + tx * 8];
        *(float4*)yp       = o0;
        *(float4*)(yp + 4) = o1;
    }
}

// ---------------------------------------------------------------------------
// Flash attention: 64 queries x 64-key tiles, 256 threads, FFMA2 inner loops.
// Q and P stored duplicated (float2) in smem for pack-free broadcast operand.
// ---------------------------------------------------------------------------
__global__ __launch_bounds__(256) void attn_kernel(
    const float* __restrict__ qkv, float* __restrict__ att)
{
    extern __shared__ char smraw[];
    float2 (*qs2)[66] = (float2(*)[66])smraw;                              // [d][i] dup
    float  (*ks)[68]  = (float(*)[68])(smraw + 64 * 66 * sizeof(float2));  // [d][j]
    float  (*vts)[68] = ks + 64;                                           // [j][d]
    float2 (*ps2)[66] = (float2(*)[66])((char*)(vts + 64));                // [j][i] dup

    const int i0 = blockIdx.x * 64;
    const int h  = blockIdx.y;
    const int b  = blockIdx.z;
    const float* qp = qkv + ((size_t)b * NOQKV + h * ND) * NL;
    const float* kp = qp + (size_t)NHID * NL;
    const float* vp = qp + (size_t)2 * NHID * NL;

    const int tid = threadIdx.x;
    const int tx  = tid & 15;    // j (S) / d (O) microtile: 4 cols = 2 pairs
    const int ty  = tid >> 4;    // i microtile: 4 rows

    // Load Q tile duplicated
    #pragma unroll
    for (int t = 0; t < 16; t++) {
        int idx = tid + t * 256;
        int i = idx & 63, d = idx >> 6;
        float v = qp[(size_t)d * NL + i0 + i];
        qs2[d][i] = make_float2(v, v);
    }
    __syncthreads();

    float m_r[4], l_r[4];
    ull o[4][2];
    #pragma unroll
    for (int r = 0; r < 4; r++) {
        m_r[r] = -1e30f; l_r[r] = 0.0f;
        o[r][0] = 0ULL;  o[r][1] = 0ULL;
    }

    const float SC = 0.125f * 1.44269504f;   // dim_head^-0.5 * log2(e)

    for (int j0 = 0; j0 < NL; j0 += 64) {
        // Load K tile [d][j] and V tile transposed [j][d]
        #pragma unroll
        for (int t = 0; t < 16; t++) {
            int idx = tid + t * 256;
            int j = idx & 63, d = idx >> 6;
            ks[d][j]  = kp[(size_t)d * NL + j0 + j];
            vts[j][d] = vp[(size_t)d * NL + j0 + j];
        }
        __syncthreads();

        // S = Q^T K  (rows i=ty*4.., col-pairs j=tx*4..)
        ull s[4][2];
        #pragma unroll
        for (int r = 0; r < 4; r++) { s[r][0] = 0ULL; s[r][1] = 0ULL; }
        #pragma unroll 8
        for (int d = 0; d < 64; d++) {
            ulonglong2 a01 = *(const ulonglong2*)&qs2[d][ty * 4];
            ulonglong2 a23 = *(const ulonglong2*)&qs2[d][ty * 4 + 2];
            ulonglong2 bb  = *(const ulonglong2*)&ks[d][tx * 4];
            ffma2(s[0][0], a01.x, bb.x); ffma2(s[0][1], a01.x, bb.y);
            ffma2(s[1][0], a01.y, bb.x); ffma2(s[1][1], a01.y, bb.y);
            ffma2(s[2][0], a23.x, bb.x); ffma2(s[2][1], a23.x, bb.y);
            ffma2(s[3][0], a23.y, bb.x); ffma2(s[3][1], a23.y, bb.y);
        }

        // Online softmax per row (row spread over 16 tx lanes)
        #pragma unroll
        for (int r = 0; r < 4; r++) {
            float2 v0 = f2unpack(s[r][0]);
            float2 v1 = f2unpack(s[r][1]);
            float s0 = v0.x * SC, s1 = v0.y * SC;
            float s2 = v1.x * SC, s3 = v1.y * SC;
            float mx = fmaxf(fmaxf(s0, s1), fmaxf(s2, s3));
            mx = fmaxf(mx, __shfl_xor_sync(0xffffffffu, mx, 1));
            mx = fmaxf(mx, __shfl_xor_sync(0xffffffffu, mx, 2));
            mx = fmaxf(mx, __shfl_xor_sync(0xffffffffu, mx, 4));
            mx = fmaxf(mx, __shfl_xor_sync(0xffffffffu, mx, 8));
            float mnew = fmaxf(m_r[r], mx);
            float corr = exp2f(m_r[r] - mnew);
            float p0 = exp2f(s0 - mnew), p1 = exp2f(s1 - mnew);
            float p2 = exp2f(s2 - mnew), p3 = exp2f(s3 - mnew);
            l_r[r] = l_r[r] * corr + (p0 + p1 + p2 + p3);
            m_r[r] = mnew;
            ull c2 = f2pack(corr, corr);
            o[r][0] = fmul2(o[r][0], c2);
            o[r][1] = fmul2(o[r][1], c2);
            ps2[tx * 4 + 0][ty * 4 + r] = make_float2(p0, p0);
            ps2[tx * 4 + 1][ty * 4 + r] = make_float2(p1, p1);
            ps2[tx * 4 + 2][ty * 4 + r] = make_float2(p2, p2);
            ps2[tx * 4 + 3][ty * 4 + r] = make_float2(p3, p3);
        }
        __syncthreads();

        // O += P * V   (rows i=ty*4.., col-pairs d=tx*4..)
        #pragma unroll 8
        for (int j = 0; j < 64; j++) {
            ulonglong2 p01 = *(const ulonglong2*)&ps2[j][ty * 4];
            ulonglong2 p23 = *(const ulonglong2*)&ps2[j][ty * 4 + 2];
            ulonglong2 vv  = *(const ulonglong2*)&vts[j][tx * 4];
            ffma2(o[0][0], p01.x, vv.x); ffma2(o[0][1], p01.x, vv.y);
            ffma2(o[1][0], p01.y, vv.x); ffma2(o[1][1], p01.y, vv.y);
            ffma2(o[2][0], p23.x, vv.x); ffma2(o[2][1], p23.x, vv.y);
            ffma2(o[3][0], p23.y, vv.x); ffma2(o[3][1], p23.y, vv.y);
        }
        __syncthreads();
    }

    // Finalize: full row denominator, normalize, transpose via smem (reuse ks)
    #pragma unroll
    for (int r = 0; r < 4; r++) {
        float lf = l_r[r];
        lf += __shfl_xor_sync(0xffffffffu, lf, 1);
        lf += __shfl_xor_sync(0xffffffffu, lf, 2);
        lf += __shfl_xor_sync(0xffffffffu, lf, 4);
        lf += __shfl_xor_sync(0xffffffffu, lf, 8);
        float inv = __fdividef(1.0f, lf);
        float2 oa = f2unpack(o[r][0]);
        float2 ob = f2unpack(o[r][1]);
        ks[tx * 4 + 0][ty * 4 + r] = oa.x * inv;
        ks[tx * 4 + 1][ty * 4 + r] = oa.y * inv;
        ks[tx * 4 + 2][ty * 4 + r] = ob.x * inv;
        ks[tx * 4 + 3][ty * 4 + r] = ob.y * inv;
    }
    __syncthreads();

    float* ap = att + ((size_t)b * NHID + h * ND) * NL + i0;
    #pragma unroll
    for (int t = 0; t < 16; t++) {
        int idx = tid + t * 256;
        int i = idx & 63, d = idx >> 6;
        ap[(size_t)d * NL + i] = ks[d][i];
    }
}

// ---------------------------------------------------------------------------
extern "C" void kernel_launch(void* const* d_in, const int* in_sizes, int n_in,
                              void* d_out, int out_size)
{
    const float* x     = (const float*)d_in[0];   // [8,512,2048]
    const float* w_qkv = (const float*)d_in[1];   // [1536,512]
    const float* w_out = (const float*)d_in[2];   // [512,512]
    const float* b_out = (const float*)d_in[3];   // [512]
    float* out = (float*)d_out;                   // [8,512,2048]

    float *qkv, *att;
    cudaGetSymbolAddress((void**)&qkv, g_qkv);
    cudaGetSymbolAddress((void**)&att, g_att);

    // 1) QKV projection
    gemm_kernel<NOQKV, NC, false>
        <<<dim3(NL / 128, NOQKV / 128, NB), 256>>>(w_qkv, x, nullptr, qkv);

    // 2) Attention
    int smem = 64 * 66 * (int)sizeof(float2) * 2 + 64 * 68 * (int)sizeof(float) * 2; // 102400
    cudaFuncSetAttribute(attn_kernel,
                         cudaFuncAttributeMaxDynamicSharedMemorySize, smem);
    attn_kernel<<<dim3(NL / 64, NH, NB), 256, smem>>>(qkv, att);

    // 3) Output projection + bias
    gemm_kernel<NC, NHID, true>
        <<<dim3(NL / 128, NC / 128, NB), 256>>>(w_out, att, b_out, out);
}

// round 3
// speedup vs baseline: 1.4572x; 1.4572x over previous
#include <cuda_runtime.h>

#define NB    8
#define NC    512
#define NL    2048
#define NH    8
#define ND    64
#define NHID  512
#define NOQKV 1536

// Scratch (device globals — allocation-free per harness rules)
__device__ float g_qkv[(size_t)NB * NOQKV * NL];   // [b][1536][2048]
__device__ float g_att[(size_t)NB * NHID * NL];    // [b][512][2048]

__device__ __forceinline__ float ex2(float x) {
    float y; asm("ex2.approx.f32 %0, %1;" : "=f"(y) : "f"(x)); return y;
}

// ---------------------------------------------------------------------------
// Tiled fp32 GEMM:  Y[b][m][l] = sum_c W[m][c] * X[b][c][l]  (+ bias[m])
// 128x128 block tile, K-tile 16, 256 threads, 8x8 microtile (two 4-wide
// halves 64 apart -> conflict-free 16B-stride LDS.128), plain FFMA.
// ---------------------------------------------------------------------------
template<int M, int K, bool HAS_BIAS>
__global__ __launch_bounds__(256, 2) void gemm_kernel(
    const float* __restrict__ W, const float* __restrict__ X,
    const float* __restrict__ bias, float* __restrict__ Y)
{
    __shared__ float As[16][132];   // [kk][m]
    __shared__ float Bs[16][132];   // [kk][n]

    const int b  = blockIdx.z;
    const int m0 = blockIdx.y * 128;
    const int n0 = blockIdx.x * 128;
    const float* Xb = X + (size_t)b * K * NL;
    float*       Yb = Y + (size_t)b * M * NL;

    const int tid = threadIdx.x;
    const int tx  = tid & 15;          // n microtile base (cols tx*4 and 64+tx*4)
    const int ty  = tid >> 4;          // m microtile base (rows ty*4 and 64+ty*4)

    const int am  = tid >> 1;          // 0..127
    const int akq = (tid & 1) * 8;     // 0 or 8
    const int bkk = tid >> 4;          // 0..15
    const int bnq = (tid & 15) * 8;    // 0..120

    float acc[8][8];
    #pragma unroll
    for (int r = 0; r < 8; r++)
        #pragma unroll
        for (int c = 0; c < 8; c++) acc[r][c] = 0.0f;

    for (int k0 = 0; k0 < K; k0 += 16) {
        // A tile: 8 consecutive k of one W row, scatter to [kk][m]
        {
            const float* wp = &W[(size_t)(m0 + am) * K + k0 + akq];
            float4 w0 = *(const float4*)wp;
            float4 w1 = *(const float4*)(wp + 4);
            As[akq + 0][am] = w0.x;  As[akq + 1][am] = w0.y;
            As[akq + 2][am] = w0.z;  As[akq + 3][am] = w0.w;
            As[akq + 4][am] = w1.x;  As[akq + 5][am] = w1.y;
            As[akq + 6][am] = w1.z;  As[akq + 7][am] = w1.w;
        }
        // B tile: coalesced along l
        {
            const float* xp = &Xb[(size_t)(k0 + bkk) * NL + n0 + bnq];
            *(float4*)&Bs[bkk][bnq]     = *(const float4*)xp;
            *(float4*)&Bs[bkk][bnq + 4] = *(const float4*)(xp + 4);
        }
        __syncthreads();

        #pragma unroll
        for (int kk = 0; kk < 16; kk++) {
            float4 a0 = *(const float4*)&As[kk][ty * 4];
            float4 a1 = *(const float4*)&As[kk][64 + ty * 4];
            float4 b0 = *(const float4*)&Bs[kk][tx * 4];
            float4 b1 = *(const float4*)&Bs[kk][64 + tx * 4];
            float av[8] = {a0.x, a0.y, a0.z, a0.w, a1.x, a1.y, a1.z, a1.w};
            float bv[8] = {b0.x, b0.y, b0.z, b0.w, b1.x, b1.y, b1.z, b1.w};
            #pragma unroll
            for (int r = 0; r < 8; r++)
                #pragma unroll
                for (int c = 0; c < 8; c++)
                    acc[r][c] += av[r] * bv[c];
        }
        __syncthreads();
    }

    #pragma unroll
    for (int g = 0; g < 2; g++) {
        #pragma unroll
        for (int r = 0; r < 4; r++) {
            int m = m0 + g * 64 + ty * 4 + r;
            float bval = HAS_BIAS ? bias[m] : 0.0f;
            int rr = g * 4 + r;
            float4 o0 = make_float4(acc[rr][0] + bval, acc[rr][1] + bval,
                                    acc[rr][2] + bval, acc[rr][3] + bval);
            float4 o1 = make_float4(acc[rr][4] + bval, acc[rr][5] + bval,
                                    acc[rr][6] + bval, acc[rr][7] + bval);
            float* yp = &Yb[(size_t)m * NL + n0];
            *(float4*)(yp + tx * 4)      = o0;
            *(float4*)(yp + 64 + tx * 4) = o1;
        }
    }
}

// ---------------------------------------------------------------------------
// Flash attention: BM=128 queries x BN=64 key tiles, 256 threads.
// Microtile: 8 query rows (two 4-row halves 64 apart) x 4 key/dim cols.
// q,k,v stored [d][l] in g_qkv; output written [d][l] into g_att.
// ---------------------------------------------------------------------------
__global__ __launch_bounds__(256, 2) void attn_kernel(
    const float* __restrict__ qkv, float* __restrict__ att)
{
    extern __shared__ float sm[];
    float (*qs)[132]  = (float(*)[132])sm;        // [d][i]  i=0..127
    float (*ps)[132]  = qs + 64;                  // [j][i]
    float (*ks)[68]   = (float(*)[68])(ps + 64);  // [d][j]
    float (*vts)[68]  = ks + 64;                  // [j][d]

    const int i0 = blockIdx.x * 128;
    const int h  = blockIdx.y;
    const int b  = blockIdx.z;
    const float* qp = qkv + ((size_t)b * NOQKV + h * ND) * NL;
    const float* kp = qp + (size_t)NHID * NL;
    const float* vp = qp + (size_t)2 * NHID * NL;

    const int tid = threadIdx.x;
    const int tx  = tid & 15;    // j (S) / d (O) cols: tx*4..tx*4+3
    const int ty  = tid >> 4;    // i rows: ty*4.. and 64+ty*4..

    // Load Q tile [d][i], coalesced along i
    #pragma unroll
    for (int t = 0; t < 32; t++) {
        int idx = tid + t * 256;
        int i = idx & 127, d = idx >> 7;
        qs[d][i] = qp[(size_t)d * NL + i0 + i];
    }
    __syncthreads();

    float m_r[8], l_r[8], o[8][4];
    #pragma unroll
    for (int r = 0; r < 8; r++) {
        m_r[r] = -1e30f; l_r[r] = 0.0f;
        #pragma unroll
        for (int c = 0; c < 4; c++) o[r][c] = 0.0f;
    }

    const float SC = 0.125f * 1.44269504f;   // dim_head^-0.5 * log2(e)

    for (int j0 = 0; j0 < NL; j0 += 64) {
        // Load K tile [d][j] and V tile transposed [j][d]
        #pragma unroll
        for (int t = 0; t < 16; t++) {
            int idx = tid + t * 256;
            int j = idx & 63, d = idx >> 6;
            float kv = kp[(size_t)d * NL + j0 + j];
            float vv = vp[(size_t)d * NL + j0 + j];
            ks[d][j]  = kv;
            vts[j][d] = vv;
        }
        __syncthreads();

        // S = Q^T K : 8 rows x 4 cols per thread
        float s[8][4];
        #pragma unroll
        for (int r = 0; r < 8; r++)
            #pragma unroll
            for (int c = 0; c < 4; c++) s[r][c] = 0.0f;

        #pragma unroll 4
        for (int d = 0; d < 64; d++) {
            float4 a0 = *(const float4*)&qs[d][ty * 4];
            float4 a1 = *(const float4*)&qs[d][64 + ty * 4];
            float4 bv = *(const float4*)&ks[d][tx * 4];
            float av[8] = {a0.x, a0.y, a0.z, a0.w, a1.x, a1.y, a1.z, a1.w};
            #pragma unroll
            for (int r = 0; r < 8; r++) {
                s[r][0] += av[r] * bv.x; s[r][1] += av[r] * bv.y;
                s[r][2] += av[r] * bv.z; s[r][3] += av[r] * bv.w;
            }
        }

        // Online softmax per row (each row spread over the 16 tx lanes)
        #pragma unroll
        for (int r = 0; r < 8; r++) {
            int irow = (r >> 2) * 64 + ty * 4 + (r & 3);
            float s0 = s[r][0] * SC, s1 = s[r][1] * SC;
            float s2 = s[r][2] * SC, s3 = s[r][3] * SC;
            float mx = fmaxf(fmaxf(s0, s1), fmaxf(s2, s3));
            mx = fmaxf(mx, __shfl_xor_sync(0xffffffffu, mx, 1));
            mx = fmaxf(mx, __shfl_xor_sync(0xffffffffu, mx, 2));
            mx = fmaxf(mx, __shfl_xor_sync(0xffffffffu, mx, 4));
            mx = fmaxf(mx, __shfl_xor_sync(0xffffffffu, mx, 8));
            float mnew = fmaxf(m_r[r], mx);
            float corr = ex2(m_r[r] - mnew);
            float p0 = ex2(s0 - mnew), p1 = ex2(s1 - mnew);
            float p2 = ex2(s2 - mnew), p3 = ex2(s3 - mnew);
            l_r[r] = l_r[r] * corr + (p0 + p1 + p2 + p3);
            m_r[r] = mnew;
            o[r][0] *= corr; o[r][1] *= corr; o[r][2] *= corr; o[r][3] *= corr;
            ps[tx * 4 + 0][irow] = p0;
            ps[tx * 4 + 1][irow] = p1;
            ps[tx * 4 + 2][irow] = p2;
            ps[tx * 4 + 3][irow] = p3;
        }
        __syncthreads();

        // O += P * V : 8 rows x 4 d-cols per thread
        #pragma unroll 4
        for (int j = 0; j < 64; j++) {
            float4 p0 = *(const float4*)&ps[j][ty * 4];
            float4 p1 = *(const float4*)&ps[j][64 + ty * 4];
            float4 vv = *(const float4*)&vts[j][tx * 4];
            float pv[8] = {p0.x, p0.y, p0.z, p0.w, p1.x, p1.y, p1.z, p1.w};
            #pragma unroll
            for (int r = 0; r < 8; r++) {
                o[r][0] += pv[r] * vv.x; o[r][1] += pv[r] * vv.y;
                o[r][2] += pv[r] * vv.z; o[r][3] += pv[r] * vv.w;
            }
        }
        __syncthreads();
    }

    // Finalize: row denominators, normalize, transpose via smem (reuse qs)
    #pragma unroll
    for (int r = 0; r < 8; r++) {
        float lf = l_r[r];
        lf += __shfl_xor_sync(0xffffffffu, lf, 1);
        lf += __shfl_xor_sync(0xffffffffu, lf, 2);
        lf += __shfl_xor_sync(0xffffffffu, lf, 4);
        lf += __shfl_xor_sync(0xffffffffu, lf, 8);
        float inv = __fdividef(1.0f, lf);
        int irow = (r >> 2) * 64 + ty * 4 + (r & 3);
        qs[tx * 4 + 0][irow] = o[r][0] * inv;
        qs[tx * 4 + 1][irow] = o[r][1] * inv;
        qs[tx * 4 + 2][irow] = o[r][2] * inv;
        qs[tx * 4 + 3][irow] = o[r][3] * inv;
    }
    __syncthreads();

    float* ap = att + ((size_t)b * NHID + h * ND) * NL + i0;
    #pragma unroll
    for (int t = 0; t < 32; t++) {
        int idx = tid + t * 256;
        int i = idx & 127, d = idx >> 7;
        ap[(size_t)d * NL + i] = qs[d][i];
    }
}

// ---------------------------------------------------------------------------
extern "C" void kernel_launch(void* const* d_in, const int* in_sizes, int n_in,
                              void* d_out, int out_size)
{
    const float* x     = (const float*)d_in[0];   // [8,512,2048]
    const float* w_qkv = (const float*)d_in[1];   // [1536,512]
    const float* w_out = (const float*)d_in[2];   // [512,512]
    const float* b_out = (const float*)d_in[3];   // [512]
    float* out = (float*)d_out;                   // [8,512,2048]

    float *qkv, *att;
    cudaGetSymbolAddress((void**)&qkv, g_qkv);
    cudaGetSymbolAddress((void**)&att, g_att);

    // 1) QKV projection
    gemm_kernel<NOQKV, NC, false>
        <<<dim3(NL / 128, NOQKV / 128, NB), 256>>>(w_qkv, x, nullptr, qkv);

    // 2) Attention
    int smem = (64 * 132 * 2 + 64 * 68 * 2) * (int)sizeof(float);  // 102400 B
    cudaFuncSetAttribute(attn_kernel,
                         cudaFuncAttributeMaxDynamicSharedMemorySize, smem);
    attn_kernel<<<dim3(NL / 128, NH, NB), 256, smem>>>(qkv, att);

    // 3) Output projection + bias
    gemm_kernel<NC, NHID, true>
        <<<dim3(NL / 128, NC / 128, NB), 256>>>(w_out, att, b_out, out);
}

// round 4
// speedup vs baseline: 1.6951x; 1.1633x over previous
#include <cuda_runtime.h>
#include <cuda_bf16.h>

#define NB    8
#define NC    512
#define NL    2048
#define NH    8
#define ND    64
#define NHID  512
#define NOQKV 1536

// Scratch (device globals — allocation-free per harness rules)
__device__ float g_qkv[(size_t)NB * NOQKV * NL];   // [b][1536][2048]
__device__ float g_att[(size_t)NB * NHID * NL];    // [b][512][2048]

__device__ __forceinline__ float ex2(float x) {
    float y; asm("ex2.approx.f32 %0, %1;" : "=f"(y) : "f"(x)); return y;
}
// pack two fp32 -> bf16x2 register {lo, hi}
__device__ __forceinline__ unsigned pckbf(float lo, float hi) {
    unsigned r; asm("cvt.rn.bf16x2.f32 %0, %1, %2;" : "=r"(r) : "f"(hi), "f"(lo)); return r;
}
// round-trip through bf16 (the "hi" part as fp32)
__device__ __forceinline__ float bfrt(float x) {
    float r;
    asm("{.reg .b16 t; cvt.rn.bf16.f32 t, %1; cvt.f32.bf16 %0, t;}" : "=f"(r) : "f"(x));
    return r;
}

#define LDSMX4(R0,R1,R2,R3,A) \
    asm volatile("ldmatrix.sync.aligned.m8n8.x4.shared.b16 {%0,%1,%2,%3}, [%4];" \
        : "=r"(R0),"=r"(R1),"=r"(R2),"=r"(R3) : "r"(A))
#define LDSMX4T(R0,R1,R2,R3,A) \
    asm volatile("ldmatrix.sync.aligned.m8n8.x4.trans.shared.b16 {%0,%1,%2,%3}, [%4];" \
        : "=r"(R0),"=r"(R1),"=r"(R2),"=r"(R3) : "r"(A))
#define MMABF(C,A0,A1,A2,A3,B0,B1) \
    asm volatile("mma.sync.aligned.m16n8k16.row.col.f32.bf16.bf16.f32 " \
        "{%0,%1,%2,%3},{%4,%5,%6,%7},{%8,%9},{%0,%1,%2,%3};" \
        : "+f"(C[0]),"+f"(C[1]),"+f"(C[2]),"+f"(C[3]) \
        : "r"(A0),"r"(A1),"r"(A2),"r"(A3),"r"(B0),"r"(B1))

// ---------------------------------------------------------------------------
// Tiled fp32 GEMM (unchanged from R3): Y[b][m][l] = W[m][:]·X[b][:][l] (+bias)
// ---------------------------------------------------------------------------
template<int M, int K, bool HAS_BIAS>
__global__ __launch_bounds__(256, 2) void gemm_kernel(
    const float* __restrict__ W, const float* __restrict__ X,
    const float* __restrict__ bias, float* __restrict__ Y)
{
    __shared__ float As[16][132];
    __shared__ float Bs[16][132];

    const int b  = blockIdx.z;
    const int m0 = blockIdx.y * 128;
    const int n0 = blockIdx.x * 128;
    const float* Xb = X + (size_t)b * K * NL;
    float*       Yb = Y + (size_t)b * M * NL;

    const int tid = threadIdx.x;
    const int tx  = tid & 15;
    const int ty  = tid >> 4;

    const int am  = tid >> 1;
    const int akq = (tid & 1) * 8;
    const int bkk = tid >> 4;
    const int bnq = (tid & 15) * 8;

    float acc[8][8];
    #pragma unroll
    for (int r = 0; r < 8; r++)
        #pragma unroll
        for (int c = 0; c < 8; c++) acc[r][c] = 0.0f;

    for (int k0 = 0; k0 < K; k0 += 16) {
        {
            const float* wp = &W[(size_t)(m0 + am) * K + k0 + akq];
            float4 w0 = *(const float4*)wp;
            float4 w1 = *(const float4*)(wp + 4);
            As[akq + 0][am] = w0.x;  As[akq + 1][am] = w0.y;
            As[akq + 2][am] = w0.z;  As[akq + 3][am] = w0.w;
            As[akq + 4][am] = w1.x;  As[akq + 5][am] = w1.y;
            As[akq + 6][am] = w1.z;  As[akq + 7][am] = w1.w;
        }
        {
            const float* xp = &Xb[(size_t)(k0 + bkk) * NL + n0 + bnq];
            *(float4*)&Bs[bkk][bnq]     = *(const float4*)xp;
            *(float4*)&Bs[bkk][bnq + 4] = *(const float4*)(xp + 4);
        }
        __syncthreads();

        #pragma unroll
        for (int kk = 0; kk < 16; kk++) {
            float4 a0 = *(const float4*)&As[kk][ty * 4];
            float4 a1 = *(const float4*)&As[kk][64 + ty * 4];
            float4 b0 = *(const float4*)&Bs[kk][tx * 4];
            float4 b1 = *(const float4*)&Bs[kk][64 + tx * 4];
            float av[8] = {a0.x, a0.y, a0.z, a0.w, a1.x, a1.y, a1.z, a1.w};
            float bv[8] = {b0.x, b0.y, b0.z, b0.w, b1.x, b1.y, b1.z, b1.w};
            #pragma unroll
            for (int r = 0; r < 8; r++)
                #pragma unroll
                for (int c = 0; c < 8; c++)
                    acc[r][c] += av[r] * bv[c];
        }
        __syncthreads();
    }

    #pragma unroll
    for (int g = 0; g < 2; g++) {
        #pragma unroll
        for (int r = 0; r < 4; r++) {
            int m = m0 + g * 64 + ty * 4 + r;
            float bval = HAS_BIAS ? bias[m] : 0.0f;
            int rr = g * 4 + r;
            float4 o0 = make_float4(acc[rr][0] + bval, acc[rr][1] + bval,
                                    acc[rr][2] + bval, acc[rr][3] + bval);
            float4 o1 = make_float4(acc[rr][4] + bval, acc[rr][5] + bval,
                                    acc[rr][6] + bval, acc[rr][7] + bval);
            float* yp = &Yb[(size_t)m * NL + n0];
            *(float4*)(yp + tx * 4)      = o0;
            *(float4*)(yp + 64 + tx * 4) = o1;
        }
    }
}

// ---------------------------------------------------------------------------
// Flash attention, bf16 tensor cores with hi/lo split (3-MMA products).
// CTA: 128 threads = 4 warps, BM=64 queries (warp w owns rows 16w..16w+15),
// BN=64 keys per iteration, D=64. Tiles in smem as [d][l] bf16 hi/lo.
// ---------------------------------------------------------------------------
// load 64x64 fp32 tile (rows d, 2048-stride) -> split bf16 hi/lo smem [d][72]
__device__ __forceinline__ void ldcvt(const float* __restrict__ src, int col0,
                                      unsigned* hi, unsigned* lo, int tid, float sc)
{
    #pragma unroll
    for (int t = 0; t < 8; t++) {
        int idx = tid + t * 128;
        int d   = idx >> 4;
        int i4  = (idx & 15) << 2;
        float4 f = *(const float4*)(src + (size_t)d * NL + col0 + i4);
        f.x *= sc; f.y *= sc; f.z *= sc; f.w *= sc;
        int off = (d * 72 + i4) >> 1;
        hi[off]     = pckbf(f.x, f.y);
        hi[off + 1] = pckbf(f.z, f.w);
        lo[off]     = pckbf(f.x - bfrt(f.x), f.y - bfrt(f.y));
        lo[off + 1] = pckbf(f.z - bfrt(f.z), f.w - bfrt(f.w));
    }
}

__global__ __launch_bounds__(128) void attn_kernel(
    const float* __restrict__ qkv, float* __restrict__ att)
{
    extern __shared__ __align__(16) unsigned smu[];
    // bf16 tiles, each 64 rows x 72 cols (=4608 bf16 = 2304 uints = 9216 B)
    unsigned* qh = smu;
    unsigned* ql = smu + 2304;
    unsigned* kh = smu + 4608;
    unsigned* kl = smu + 6912;
    unsigned* vh = smu + 9216;
    unsigned* vl = smu + 11520;

    const int tid  = threadIdx.x;
    const int lane = tid & 31;
    const int warp = tid >> 5;
    const int i0 = blockIdx.x * 64;
    const int h  = blockIdx.y;
    const int b  = blockIdx.z;

    const float* qp = qkv + ((size_t)b * NOQKV + h * ND) * NL;
    const float* kp = qp + (size_t)NHID * NL;
    const float* vp = qp + (size_t)2 * NHID * NL;

    unsigned sbase = (unsigned)__cvta_generic_to_shared(smu);
    const unsigned QH = sbase, QL = sbase + 9216, KH = sbase + 18432,
                   KL = sbase + 27648, VH = sbase + 36864, VL = sbase + 46080;

    // ldmatrix per-thread address components (row stride = 144 B)
    // Q (A-frag, trans on [d][i]):
    const unsigned offQ = (((lane >> 4) & 1) * 8 + (lane & 7)) * 144
                        + (warp * 16 + ((lane >> 3) & 1) * 8) * 2;
    // K (B-frag, trans on [d][j]):
    const unsigned offK = (((lane >> 3) & 1) * 8 + (lane & 7)) * 144
                        + (((lane >> 4) & 1) * 8) * 2;
    // V (B-frag, non-trans on [d][j]):
    const unsigned offV = (((lane >> 4) & 1) * 8 + (lane & 7)) * 144
                        + (((lane >> 3) & 1) * 8) * 2;

    const float SC = 0.125f * 1.44269504f;   // dim_head^-0.5 * log2(e), folded into Q

    // Load Q tile once (scaled)
    ldcvt(qp, i0, qh, ql, tid, SC);
    __syncthreads();

    float o[8][4];
    #pragma unroll
    for (int t = 0; t < 8; t++) { o[t][0]=0; o[t][1]=0; o[t][2]=0; o[t][3]=0; }
    float m0 = -1e30f, m1 = -1e30f, l0 = 0.0f, l1 = 0.0f;

    for (int j0 = 0; j0 < NL; j0 += 64) {
        ldcvt(kp, j0, kh, kl, tid, 1.0f);
        ldcvt(vp, j0, vh, vl, tid, 1.0f);
        __syncthreads();

        // ---- S = Q K^T (m16 x n64 per warp), 3-MMA split ----
        float s[8][4];
        #pragma unroll
        for (int t = 0; t < 8; t++) { s[t][0]=0; s[t][1]=0; s[t][2]=0; s[t][3]=0; }

        #pragma unroll
        for (int kc = 0; kc < 4; kc++) {
            unsigned kcb = kc * 16 * 144;
            unsigned qa0,qa1,qa2,qa3, qb0,qb1,qb2,qb3;
            LDSMX4T(qa0,qa1,qa2,qa3, QH + offQ + kcb);
            LDSMX4T(qb0,qb1,qb2,qb3, QL + offQ + kcb);
            #pragma unroll
            for (int p = 0; p < 4; p++) {
                unsigned nb = p * 32;  // n0 = 16p -> bytes
                unsigned h0,h1,h2,h3, e0,e1,e2,e3;
                LDSMX4T(h0,h1,h2,h3, KH + offK + kcb + nb);
                LDSMX4T(e0,e1,e2,e3, KL + offK + kcb + nb);
                MMABF(s[2*p],   qa0,qa1,qa2,qa3, h0,h1);
                MMABF(s[2*p],   qa0,qa1,qa2,qa3, e0,e1);
                MMABF(s[2*p],   qb0,qb1,qb2,qb3, h0,h1);
                MMABF(s[2*p+1], qa0,qa1,qa2,qa3, h2,h3);
                MMABF(s[2*p+1], qa0,qa1,qa2,qa3, e2,e3);
                MMABF(s[2*p+1], qb0,qb1,qb2,qb3, h2,h3);
            }
        }

        // ---- online softmax (rows r0=lane>>2, r1=r0+8; cols over quad) ----
        float mx0 = -1e30f, mx1 = -1e30f;
        #pragma unroll
        for (int t = 0; t < 8; t++) {
            mx0 = fmaxf(mx0, fmaxf(s[t][0], s[t][1]));
            mx1 = fmaxf(mx1, fmaxf(s[t][2], s[t][3]));
        }
        mx0 = fmaxf(mx0, __shfl_xor_sync(0xffffffffu, mx0, 1));
        mx0 = fmaxf(mx0, __shfl_xor_sync(0xffffffffu, mx0, 2));
        mx1 = fmaxf(mx1, __shfl_xor_sync(0xffffffffu, mx1, 1));
        mx1 = fmaxf(mx1, __shfl_xor_sync(0xffffffffu, mx1, 2));
        float mn0 = fmaxf(m0, mx0), mn1 = fmaxf(m1, mx1);
        float c0 = ex2(m0 - mn0),   c1 = ex2(m1 - mn1);
        m0 = mn0; m1 = mn1;

        float rs0 = 0.0f, rs1 = 0.0f;
        #pragma unroll
        for (int t = 0; t < 8; t++) {
            s[t][0] = ex2(s[t][0] - mn0);
            s[t][1] = ex2(s[t][1] - mn0);
            s[t][2] = ex2(s[t][2] - mn1);
            s[t][3] = ex2(s[t][3] - mn1);
            rs0 += s[t][0] + s[t][1];
            rs1 += s[t][2] + s[t][3];
        }
        l0 = l0 * c0 + rs0;
        l1 = l1 * c1 + rs1;
        #pragma unroll
        for (int t = 0; t < 8; t++) {
            o[t][0] *= c0; o[t][1] *= c0; o[t][2] *= c1; o[t][3] *= c1;
        }

        // ---- P fragments (hi/lo) straight from S registers ----
        unsigned pah[4][4], pal[4][4];
        #pragma unroll
        for (int c = 0; c < 4; c++) {
            int A = 2 * c, B = 2 * c + 1;
            pah[c][0] = pckbf(s[A][0], s[A][1]);
            pah[c][1] = pckbf(s[A][2], s[A][3]);
            pah[c][2] = pckbf(s[B][0], s[B][1]);
            pah[c][3] = pckbf(s[B][2], s[B][3]);
            pal[c][0] = pckbf(s[A][0]-bfrt(s[A][0]), s[A][1]-bfrt(s[A][1]));
            pal[c][1] = pckbf(s[A][2]-bfrt(s[A][2]), s[A][3]-bfrt(s[A][3]));
            pal[c][2] = pckbf(s[B][0]-bfrt(s[B][0]), s[B][1]-bfrt(s[B][1]));
            pal[c][3] = pckbf(s[B][2]-bfrt(s[B][2]), s[B][3]-bfrt(s[B][3]));
        }

        // ---- O += P V (k = j in chunks of 16) ----
        #pragma unroll
        for (int c = 0; c < 4; c++) {
            unsigned jb = c * 32;  // jc = 16c -> col bytes
            #pragma unroll
            for (int p = 0; p < 4; p++) {
                unsigned db = p * 2304;  // d0 = 16p -> row bytes (16*144)
                unsigned h0,h1,h2,h3, e0,e1,e2,e3;
                LDSMX4(h0,h1,h2,h3, VH + offV + db + jb);
                LDSMX4(e0,e1,e2,e3, VL + offV + db + jb);
                MMABF(o[2*p],   pah[c][0],pah[c][1],pah[c][2],pah[c][3], h0,h1);
                MMABF(o[2*p],   pah[c][0],pah[c][1],pah[c][2],pah[c][3], e0,e1);
                MMABF(o[2*p],   pal[c][0],pal[c][1],pal[c][2],pal[c][3], h0,h1);
                MMABF(o[2*p+1], pah[c][0],pah[c][1],pah[c][2],pah[c][3], h2,h3);
                MMABF(o[2*p+1], pah[c][0],pah[c][1],pah[c][2],pah[c][3], e2,e3);
                MMABF(o[2*p+1], pal[c][0],pal[c][1],pal[c][2],pal[c][3], h2,h3);
            }
        }
        __syncthreads();
    }

    // ---- finalize: reduce l over quad, normalize, store [d][i] fp32 ----
    l0 += __shfl_xor_sync(0xffffffffu, l0, 1);
    l0 += __shfl_xor_sync(0xffffffffu, l0, 2);
    l1 += __shfl_xor_sync(0xffffffffu, l1, 1);
    l1 += __shfl_xor_sync(0xffffffffu, l1, 2);
    float inv0 = __fdividef(1.0f, l0);
    float inv1 = __fdividef(1.0f, l1);

    float* ab = att + ((size_t)b * NHID + h * ND) * NL;
    int ig = i0 + warp * 16 + (lane >> 2);
    #pragma unroll
    for (int dt = 0; dt < 8; dt++) {
        int d = dt * 8 + (lane & 3) * 2;
        ab[(size_t)d * NL + ig]           = o[dt][0] * inv0;
        ab[(size_t)(d + 1) * NL + ig]     = o[dt][1] * inv0;
        ab[(size_t)d * NL + ig + 8]       = o[dt][2] * inv1;
        ab[(size_t)(d + 1) * NL + ig + 8] = o[dt][3] * inv1;
    }
}

// ---------------------------------------------------------------------------
extern "C" void kernel_launch(void* const* d_in, const int* in_sizes, int n_in,
                              void* d_out, int out_size)
{
    const float* x     = (const float*)d_in[0];
    const float* w_qkv = (const float*)d_in[1];
    const float* w_out = (const float*)d_in[2];
    const float* b_out = (const float*)d_in[3];
    float* out = (float*)d_out;

    float *qkv, *att;
    cudaGetSymbolAddress((void**)&qkv, g_qkv);
    cudaGetSymbolAddress((void**)&att, g_att);

    // 1) QKV projection (SIMT fp32)
    gemm_kernel<NOQKV, NC, false>
        <<<dim3(NL / 128, NOQKV / 128, NB), 256>>>(w_qkv, x, nullptr, qkv);

    // 2) Attention (bf16 tensor cores, split precision)
    int smem = 6 * 64 * 72 * 2;   // 55296 B
    cudaFuncSetAttribute(attn_kernel,
                         cudaFuncAttributeMaxDynamicSharedMemorySize, smem);
    attn_kernel<<<dim3(NL / 64, NH, NB), 128, smem>>>(qkv, att);

    // 3) Output projection + bias (SIMT fp32)
    gemm_kernel<NC, NHID, true>
        <<<dim3(NL / 128, NC / 128, NB), 256>>>(w_out, att, b_out, out);
}

// round 5
// speedup vs baseline: 3.7264x; 2.1984x over previous
#include <cuda_runtime.h>
#include <cuda_bf16.h>

#define NB    8
#define NC    512
#define NL    2048
#define NH    8
#define ND    64
#define NHID  512
#define NOQKV 1536

// ---------------- device-global scratch (allocation-free) ----------------
__device__ __nv_bfloat16 g_xh[(size_t)NB * NC * NL];
__device__ __nv_bfloat16 g_xl[(size_t)NB * NC * NL];
__device__ __nv_bfloat16 g_wqh[(size_t)NC * NOQKV];    // [c][m] transposed
__device__ __nv_bfloat16 g_wql[(size_t)NC * NOQKV];
__device__ __nv_bfloat16 g_woh[(size_t)NHID * NC];     // [c][m] transposed
__device__ __nv_bfloat16 g_wol[(size_t)NHID * NC];
__device__ __nv_bfloat16 g_qkvh[(size_t)NB * NOQKV * NL];
__device__ __nv_bfloat16 g_qkvl[(size_t)NB * NOQKV * NL];
__device__ __nv_bfloat16 g_atth[(size_t)NB * NHID * NL];
__device__ __nv_bfloat16 g_attl[(size_t)NB * NHID * NL];

__device__ __forceinline__ float ex2(float x) {
    float y; asm("ex2.approx.f32 %0, %1;" : "=f"(y) : "f"(x)); return y;
}
// pack two fp32 -> bf16x2 {low half = first arg}
__device__ __forceinline__ unsigned pckbf(float lo, float hi) {
    unsigned r; asm("cvt.rn.bf16x2.f32 %0, %1, %2;" : "=r"(r) : "f"(hi), "f"(lo)); return r;
}
__device__ __forceinline__ float bfrt(float x) {
    float r;
    asm("{.reg .b16 t; cvt.rn.bf16.f32 t, %1; cvt.f32.bf16 %0, t;}" : "=f"(r) : "f"(x));
    return r;
}

#define LDSMX4(R0,R1,R2,R3,A) \
    asm volatile("ldmatrix.sync.aligned.m8n8.x4.shared.b16 {%0,%1,%2,%3}, [%4];" \
        : "=r"(R0),"=r"(R1),"=r"(R2),"=r"(R3) : "r"(A))
#define LDSMX4T(R0,R1,R2,R3,A) \
    asm volatile("ldmatrix.sync.aligned.m8n8.x4.trans.shared.b16 {%0,%1,%2,%3}, [%4];" \
        : "=r"(R0),"=r"(R1),"=r"(R2),"=r"(R3) : "r"(A))
#define MMABF(C,A0,A1,A2,A3,B0,B1) \
    asm volatile("mma.sync.aligned.m16n8k16.row.col.f32.bf16.bf16.f32 " \
        "{%0,%1,%2,%3},{%4,%5,%6,%7},{%8,%9},{%0,%1,%2,%3};" \
        : "+f"(C[0]),"+f"(C[1]),"+f"(C[2]),"+f"(C[3]) \
        : "r"(A0),"r"(A1),"r"(A2),"r"(A3),"r"(B0),"r"(B1))

// ---------------------------------------------------------------------------
// Elementwise fp32 -> bf16 hi/lo split (vectorized)
// ---------------------------------------------------------------------------
__global__ void cvt_split(const float4* __restrict__ src,
                          uint2* __restrict__ h, uint2* __restrict__ l)
{
    int i = blockIdx.x * blockDim.x + threadIdx.x;
    float4 f = src[i];
    uint2 hv, lv;
    hv.x = pckbf(f.x, f.y);
    hv.y = pckbf(f.z, f.w);
    lv.x = pckbf(f.x - bfrt(f.x), f.y - bfrt(f.y));
    lv.y = pckbf(f.z - bfrt(f.z), f.w - bfrt(f.w));
    h[i] = hv; l[i] = lv;
}

// fp32 W[m][c] -> transposed bf16 hi/lo [c][m]
__global__ void cvt_splitT(const float* __restrict__ w,
                           __nv_bfloat16* __restrict__ ht,
                           __nv_bfloat16* __restrict__ lt, int M, int C)
{
    int idx = blockIdx.x * blockDim.x + threadIdx.x;
    int m = idx / C, c = idx % C;
    float v = w[idx];
    float hi = bfrt(v);
    ht[(size_t)c * M + m] = __float2bfloat16(hi);
    lt[(size_t)c * M + m] = __float2bfloat16(v - hi);
}

// ---------------------------------------------------------------------------
// bf16 split-MMA GEMM: Y[b][m][n] = sum_k A[k][m] * B[b][k][n]  (+ bias[m])
// Block 128m x 128n, k-tile 32, 256 threads (8 warps, 2x4 m-n warp grid).
// Each product = Ah*Bh + Ah*Bl + Al*Bh (3 MMAs). SPLIT_OUT: write bf16 hi/lo.
// ---------------------------------------------------------------------------
template<int M, int K, bool HAS_BIAS, bool SPLIT_OUT>
__global__ __launch_bounds__(256) void gemm_bf16(
    const __nv_bfloat16* __restrict__ Ah_g, const __nv_bfloat16* __restrict__ Al_g,
    const __nv_bfloat16* __restrict__ Bh_g, const __nv_bfloat16* __restrict__ Bl_g,
    const float* __restrict__ bias,
    __nv_bfloat16* __restrict__ Yh, __nv_bfloat16* __restrict__ Yl,
    float* __restrict__ Yf)
{
    __shared__ __align__(16) unsigned char smg[4 * 32 * 272];
    __nv_bfloat16* Ah_s = (__nv_bfloat16*)smg;
    __nv_bfloat16* Al_s = Ah_s + 32 * 136;
    __nv_bfloat16* Bh_s = Ah_s + 2 * 32 * 136;
    __nv_bfloat16* Bl_s = Ah_s + 3 * 32 * 136;

    const int b  = blockIdx.z;
    const int m0 = blockIdx.y * 128;
    const int n0 = blockIdx.x * 128;

    const int tid  = threadIdx.x;
    const int lane = tid & 31;
    const int warp = tid >> 5;
    const int wm   = warp >> 2;          // 0..1 -> m offset wm*64
    const int wn   = warp & 3;           // 0..3 -> n offset wn*32

    unsigned sb = (unsigned)__cvta_generic_to_shared(smg);
    const unsigned SAH = sb, SAL = sb + 8704, SBH = sb + 17408, SBL = sb + 26112;

    // ldmatrix per-lane offsets (row stride 272 B)
    const unsigned offA = ((((lane >> 4) & 1) * 8 + (lane & 7)) * 272)
                        + (wm * 64 + ((lane >> 3) & 1) * 8) * 2;
    const unsigned offB = ((((lane >> 3) & 1) * 8 + (lane & 7)) * 272)
                        + (wn * 32 + ((lane >> 4) & 1) * 8) * 2;

    float acc[4][4][4];
    #pragma unroll
    for (int i = 0; i < 4; i++)
        #pragma unroll
        for (int j = 0; j < 4; j++)
            #pragma unroll
            for (int t = 0; t < 4; t++) acc[i][j][t] = 0.0f;

    for (int k0 = 0; k0 < K; k0 += 32) {
        #pragma unroll
        for (int p = 0; p < 2; p++) {
            int q   = tid + p * 256;
            int row = q >> 4;
            int c8  = (q & 15) * 8;
            size_t ga = (size_t)(k0 + row) * M + m0 + c8;
            size_t gb = ((size_t)b * K + k0 + row) * NL + n0 + c8;
            unsigned so = row * 136 + c8;
            *(uint4*)(Ah_s + so) = *(const uint4*)(Ah_g + ga);
            *(uint4*)(Al_s + so) = *(const uint4*)(Al_g + ga);
            *(uint4*)(Bh_s + so) = *(const uint4*)(Bh_g + gb);
            *(uint4*)(Bl_s + so) = *(const uint4*)(Bl_g + gb);
        }
        __syncthreads();

        #pragma unroll
        for (int kc = 0; kc < 2; kc++) {
            unsigned kb = kc * 16 * 272;
            unsigned bh[2][4], bl[2][4];
            LDSMX4T(bh[0][0], bh[0][1], bh[0][2], bh[0][3], SBH + offB + kb);
            LDSMX4T(bh[1][0], bh[1][1], bh[1][2], bh[1][3], SBH + offB + kb + 32);
            LDSMX4T(bl[0][0], bl[0][1], bl[0][2], bl[0][3], SBL + offB + kb);
            LDSMX4T(bl[1][0], bl[1][1], bl[1][2], bl[1][3], SBL + offB + kb + 32);
            #pragma unroll
            for (int mf = 0; mf < 4; mf++) {
                unsigned ah0,ah1,ah2,ah3, al0,al1,al2,al3;
                LDSMX4T(ah0,ah1,ah2,ah3, SAH + offA + kb + mf * 32);
                LDSMX4T(al0,al1,al2,al3, SAL + offA + kb + mf * 32);
                #pragma unroll
                for (int g = 0; g < 4; g++) {
                    unsigned b0 = bh[g >> 1][(g & 1) * 2];
                    unsigned b1 = bh[g >> 1][(g & 1) * 2 + 1];
                    unsigned c0 = bl[g >> 1][(g & 1) * 2];
                    unsigned c1 = bl[g >> 1][(g & 1) * 2 + 1];
                    MMABF(acc[mf][g], ah0,ah1,ah2,ah3, b0,b1);
                    MMABF(acc[mf][g], ah0,ah1,ah2,ah3, c0,c1);
                    MMABF(acc[mf][g], al0,al1,al2,al3, b0,b1);
                }
            }
        }
        __syncthreads();
    }

    // ---- epilogue ----
    const int r0 = lane >> 2;
    const int cp = (lane & 3) * 2;
    #pragma unroll
    for (int mf = 0; mf < 4; mf++) {
        int ml = wm * 64 + mf * 16 + r0;
        float bv0 = 0.0f, bv1 = 0.0f;
        if (HAS_BIAS) { bv0 = bias[m0 + ml]; bv1 = bias[m0 + ml + 8]; }
        #pragma unroll
        for (int g = 0; g < 4; g++) {
            int n = n0 + wn * 32 + g * 8 + cp;
            float* c = acc[mf][g];
            size_t a0 = ((size_t)b * M + m0 + ml) * NL + n;
            size_t a1 = a0 + (size_t)8 * NL;
            if (SPLIT_OUT) {
                *(unsigned*)(Yh + a0) = pckbf(c[0], c[1]);
                *(unsigned*)(Yl + a0) = pckbf(c[0] - bfrt(c[0]), c[1] - bfrt(c[1]));
                *(unsigned*)(Yh + a1) = pckbf(c[2], c[3]);
                *(unsigned*)(Yl + a1) = pckbf(c[2] - bfrt(c[2]), c[3] - bfrt(c[3]));
            } else {
                *(float2*)(Yf + a0) = make_float2(c[0] + bv0, c[1] + bv0);
                *(float2*)(Yf + a1) = make_float2(c[2] + bv1, c[3] + bv1);
            }
        }
    }
}

// ---------------------------------------------------------------------------
// Flash attention, bf16 tensor cores, pre-split hi/lo inputs (plain copies).
// CTA: 128 threads = 4 warps, BM=64 queries, BN=64 keys, D=64.
// ---------------------------------------------------------------------------
__device__ __forceinline__ void ldtile(const __nv_bfloat16* __restrict__ src,
                                       int col0, unsigned* dstu, int tid)
{
    #pragma unroll
    for (int p = 0; p < 4; p++) {
        int q   = tid + p * 128;
        int row = q >> 3;
        int c8  = (q & 7) * 8;
        *(uint4*)(dstu + row * 36 + c8 / 2) =
            *(const uint4*)(src + (size_t)row * NL + col0 + c8);
    }
}

__global__ __launch_bounds__(128) void attn_kernel(
    const __nv_bfloat16* __restrict__ qkvh, const __nv_bfloat16* __restrict__ qkvl,
    __nv_bfloat16* __restrict__ atth, __nv_bfloat16* __restrict__ attl)
{
    extern __shared__ __align__(16) unsigned smu[];
    unsigned* qh = smu;
    unsigned* ql = smu + 2304;
    unsigned* kh = smu + 4608;
    unsigned* kl = smu + 6912;
    unsigned* vh = smu + 9216;
    unsigned* vl = smu + 11520;

    const int tid  = threadIdx.x;
    const int lane = tid & 31;
    const int warp = tid >> 5;
    const int i0 = blockIdx.x * 64;
    const int h  = blockIdx.y;
    const int b  = blockIdx.z;

    const size_t base = ((size_t)b * NOQKV + h * ND) * NL;
    const __nv_bfloat16* qph = qkvh + base;
    const __nv_bfloat16* qpl = qkvl + base;
    const __nv_bfloat16* kph = qph + (size_t)NHID * NL;
    const __nv_bfloat16* kpl = qpl + (size_t)NHID * NL;
    const __nv_bfloat16* vph = qph + (size_t)2 * NHID * NL;
    const __nv_bfloat16* vpl = qpl + (size_t)2 * NHID * NL;

    unsigned sbase = (unsigned)__cvta_generic_to_shared(smu);
    const unsigned QH = sbase, QL = sbase + 9216, KH = sbase + 18432,
                   KL = sbase + 27648, VH = sbase + 36864, VL = sbase + 46080;

    const unsigned offQ = (((lane >> 4) & 1) * 8 + (lane & 7)) * 144
                        + (warp * 16 + ((lane >> 3) & 1) * 8) * 2;
    const unsigned offK = (((lane >> 3) & 1) * 8 + (lane & 7)) * 144
                        + (((lane >> 4) & 1) * 8) * 2;
    const unsigned offV = (((lane >> 4) & 1) * 8 + (lane & 7)) * 144
                        + (((lane >> 3) & 1) * 8) * 2;

    const float SC = 0.125f * 1.44269504f;   // dim_head^-0.5 * log2(e)

    ldtile(qph, i0, qh, tid);
    ldtile(qpl, i0, ql, tid);
    __syncthreads();

    float o[8][4];
    #pragma unroll
    for (int t = 0; t < 8; t++) { o[t][0]=0; o[t][1]=0; o[t][2]=0; o[t][3]=0; }
    float m0 = -1e30f, m1 = -1e30f, l0 = 0.0f, l1 = 0.0f;

    for (int j0 = 0; j0 < NL; j0 += 64) {
        ldtile(kph, j0, kh, tid);
        ldtile(kpl, j0, kl, tid);
        ldtile(vph, j0, vh, tid);
        ldtile(vpl, j0, vl, tid);
        __syncthreads();

        // ---- S = Q K^T (m16 x n64 per warp), 3-MMA split ----
        float s[8][4];
        #pragma unroll
        for (int t = 0; t < 8; t++) { s[t][0]=0; s[t][1]=0; s[t][2]=0; s[t][3]=0; }

        #pragma unroll
        for (int kc = 0; kc < 4; kc++) {
            unsigned kcb = kc * 16 * 144;
            unsigned qa0,qa1,qa2,qa3, qb0,qb1,qb2,qb3;
            LDSMX4T(qa0,qa1,qa2,qa3, QH + offQ + kcb);
            LDSMX4T(qb0,qb1,qb2,qb3, QL + offQ + kcb);
            #pragma unroll
            for (int p = 0; p < 4; p++) {
                unsigned nb = p * 32;
                unsigned h0,h1,h2,h3, e0,e1,e2,e3;
                LDSMX4T(h0,h1,h2,h3, KH + offK + kcb + nb);
                LDSMX4T(e0,e1,e2,e3, KL + offK + kcb + nb);
                MMABF(s[2*p],   qa0,qa1,qa2,qa3, h0,h1);
                MMABF(s[2*p],   qa0,qa1,qa2,qa3, e0,e1);
                MMABF(s[2*p],   qb0,qb1,qb2,qb3, h0,h1);
                MMABF(s[2*p+1], qa0,qa1,qa2,qa3, h2,h3);
                MMABF(s[2*p+1], qa0,qa1,qa2,qa3, e2,e3);
                MMABF(s[2*p+1], qb0,qb1,qb2,qb3, h2,h3);
            }
        }

        // scale
        #pragma unroll
        for (int t = 0; t < 8; t++) {
            s[t][0] *= SC; s[t][1] *= SC; s[t][2] *= SC; s[t][3] *= SC;
        }

        // ---- online softmax ----
        float mx0 = -1e30f, mx1 = -1e30f;
        #pragma unroll
        for (int t = 0; t < 8; t++) {
            mx0 = fmaxf(mx0, fmaxf(s[t][0], s[t][1]));
            mx1 = fmaxf(mx1, fmaxf(s[t][2], s[t][3]));
        }
        mx0 = fmaxf(mx0, __shfl_xor_sync(0xffffffffu, mx0, 1));
        mx0 = fmaxf(mx0, __shfl_xor_sync(0xffffffffu, mx0, 2));
        mx1 = fmaxf(mx1, __shfl_xor_sync(0xffffffffu, mx1, 1));
        mx1 = fmaxf(mx1, __shfl_xor_sync(0xffffffffu, mx1, 2));
        float mn0 = fmaxf(m0, mx0), mn1 = fmaxf(m1, mx1);
        float c0 = ex2(m0 - mn0),   c1 = ex2(m1 - mn1);
        m0 = mn0; m1 = mn1;

        float rs0 = 0.0f, rs1 = 0.0f;
        #pragma unroll
        for (int t = 0; t < 8; t++) {
            s[t][0] = ex2(s[t][0] - mn0);
            s[t][1] = ex2(s[t][1] - mn0);
            s[t][2] = ex2(s[t][2] - mn1);
            s[t][3] = ex2(s[t][3] - mn1);
            rs0 += s[t][0] + s[t][1];
            rs1 += s[t][2] + s[t][3];
        }
        l0 = l0 * c0 + rs0;
        l1 = l1 * c1 + rs1;
        #pragma unroll
        for (int t = 0; t < 8; t++) {
            o[t][0] *= c0; o[t][1] *= c0; o[t][2] *= c1; o[t][3] *= c1;
        }

        // ---- P fragments (hi/lo) straight from S registers ----
        unsigned pah[4][4], pal[4][4];
        #pragma unroll
        for (int c = 0; c < 4; c++) {
            int A = 2 * c, B = 2 * c + 1;
            pah[c][0] = pckbf(s[A][0], s[A][1]);
            pah[c][1] = pckbf(s[A][2], s[A][3]);
            pah[c][2] = pckbf(s[B][0], s[B][1]);
            pah[c][3] = pckbf(s[B][2], s[B][3]);
            pal[c][0] = pckbf(s[A][0]-bfrt(s[A][0]), s[A][1]-bfrt(s[A][1]));
            pal[c][1] = pckbf(s[A][2]-bfrt(s[A][2]), s[A][3]-bfrt(s[A][3]));
            pal[c][2] = pckbf(s[B][0]-bfrt(s[B][0]), s[B][1]-bfrt(s[B][1]));
            pal[c][3] = pckbf(s[B][2]-bfrt(s[B][2]), s[B][3]-bfrt(s[B][3]));
        }

        // ---- O += P V ----
        #pragma unroll
        for (int c = 0; c < 4; c++) {
            unsigned jb = c * 32;
            #pragma unroll
            for (int p = 0; p < 4; p++) {
                unsigned db = p * 2304;
                unsigned h0,h1,h2,h3, e0,e1,e2,e3;
                LDSMX4(h0,h1,h2,h3, VH + offV + db + jb);
                LDSMX4(e0,e1,e2,e3, VL + offV + db + jb);
                MMABF(o[2*p],   pah[c][0],pah[c][1],pah[c][2],pah[c][3], h0,h1);
                MMABF(o[2*p],   pah[c][0],pah[c][1],pah[c][2],pah[c][3], e0,e1);
                MMABF(o[2*p],   pal[c][0],pal[c][1],pal[c][2],pal[c][3], h0,h1);
                MMABF(o[2*p+1], pah[c][0],pah[c][1],pah[c][2],pah[c][3], h2,h3);
                MMABF(o[2*p+1], pah[c][0],pah[c][1],pah[c][2],pah[c][3], e2,e3);
                MMABF(o[2*p+1], pal[c][0],pal[c][1],pal[c][2],pal[c][3], h2,h3);
            }
        }
        __syncthreads();
    }

    // ---- finalize: reduce l, normalize, split, store bf16 [d][i] ----
    l0 += __shfl_xor_sync(0xffffffffu, l0, 1);
    l0 += __shfl_xor_sync(0xffffffffu, l0, 2);
    l1 += __shfl_xor_sync(0xffffffffu, l1, 1);
    l1 += __shfl_xor_sync(0xffffffffu, l1, 2);
    float inv0 = __fdividef(1.0f, l0);
    float inv1 = __fdividef(1.0f, l1);

    const size_t ob = ((size_t)b * NHID + h * ND) * NL;
    int ig = i0 + warp * 16 + (lane >> 2);
    #pragma unroll
    for (int dt = 0; dt < 8; dt++) {
        int d = dt * 8 + (lane & 3) * 2;
        float v0 = o[dt][0] * inv0, v1 = o[dt][1] * inv0;
        float v2 = o[dt][2] * inv1, v3 = o[dt][3] * inv1;
        size_t a0 = ob + (size_t)d * NL + ig;
        size_t a1 = ob + (size_t)(d + 1) * NL + ig;
        atth[a0]     = __float2bfloat16(v0);
        attl[a0]     = __float2bfloat16(v0 - bfrt(v0));
        atth[a1]     = __float2bfloat16(v1);
        attl[a1]     = __float2bfloat16(v1 - bfrt(v1));
        atth[a0 + 8] = __float2bfloat16(v2);
        attl[a0 + 8] = __float2bfloat16(v2 - bfrt(v2));
        atth[a1 + 8] = __float2bfloat16(v3);
        attl[a1 + 8] = __float2bfloat16(v3 - bfrt(v3));
    }
}

// ---------------------------------------------------------------------------
extern "C" void kernel_launch(void* const* d_in, const int* in_sizes, int n_in,
                              void* d_out, int out_size)
{
    const float* x     = (const float*)d_in[0];   // [8,512,2048]
    const float* w_qkv = (const float*)d_in[1];   // [1536,512]
    const float* w_out = (const float*)d_in[2];   // [512,512]
    const float* b_out = (const float*)d_in[3];   // [512]
    float* out = (float*)d_out;                   // [8,512,2048]

    __nv_bfloat16 *xh, *xl, *wqh, *wql, *woh, *wol, *qkvh, *qkvl, *atth, *attl;
    cudaGetSymbolAddress((void**)&xh,   g_xh);
    cudaGetSymbolAddress((void**)&xl,   g_xl);
    cudaGetSymbolAddress((void**)&wqh,  g_wqh);
    cudaGetSymbolAddress((void**)&wql,  g_wql);
    cudaGetSymbolAddress((void**)&woh,  g_woh);
    cudaGetSymbolAddress((void**)&wol,  g_wol);
    cudaGetSymbolAddress((void**)&qkvh, g_qkvh);
    cudaGetSymbolAddress((void**)&qkvl, g_qkvl);
    cudaGetSymbolAddress((void**)&atth, g_atth);
    cudaGetSymbolAddress((void**)&attl, g_attl);

    // 0) split inputs/weights
    cvt_split<<<(NB * NC * NL / 4) / 256, 256>>>(
        (const float4*)x, (uint2*)xh, (uint2*)xl);
    cvt_splitT<<<(NOQKV * NC) / 256, 256>>>(w_qkv, wqh, wql, NOQKV, NC);
    cvt_splitT<<<(NC * NHID) / 256, 256>>>(w_out, woh, wol, NC, NHID);

    // 1) QKV projection (tensor, split out)
    gemm_bf16<NOQKV, NC, false, true>
        <<<dim3(NL / 128, NOQKV / 128, NB), 256>>>(
            wqh, wql, xh, xl, nullptr, qkvh, qkvl, nullptr);

    // 2) Attention (tensor)
    int smem = 6 * 64 * 72 * 2;   // 55296 B
    cudaFuncSetAttribute(attn_kernel,
                         cudaFuncAttributeMaxDynamicSharedMemorySize, smem);
    attn_kernel<<<dim3(NL / 64, NH, NB), 128, smem>>>(qkvh, qkvl, atth, attl);

    // 3) Output projection + bias (tensor, fp32 out)
    gemm_bf16<NC, NHID, true, false>
        <<<dim3(NL / 128, NC / 128, NB), 256>>>(
            woh, wol, atth, attl, b_out, nullptr, nullptr, out);
}

// round 7
// speedup vs baseline: 4.1353x; 1.1097x over previous
#include <cuda_runtime.h>
#include <cuda_bf16.h>

#define NB    8
#define NC    512
#define NL    2048
#define NH    8
#define ND    64
#define NHID  512
#define NOQKV 1536

// ---------------- device-global scratch (allocation-free) ----------------
__device__ __nv_bfloat16 g_xh[(size_t)NB * NC * NL];
__device__ __nv_bfloat16 g_xl[(size_t)NB * NC * NL];
__device__ __nv_bfloat16 g_wqh[(size_t)NC * NOQKV];    // [c][m] transposed
__device__ __nv_bfloat16 g_wql[(size_t)NC * NOQKV];
__device__ __nv_bfloat16 g_woh[(size_t)NHID * NC];     // [c][m] transposed
__device__ __nv_bfloat16 g_wol[(size_t)NHID * NC];
__device__ __nv_bfloat16 g_qkvh[(size_t)NB * NOQKV * NL];
__device__ __nv_bfloat16 g_qkvl[(size_t)NB * NOQKV * NL];
__device__ __nv_bfloat16 g_atth[(size_t)NB * NHID * NL];
__device__ __nv_bfloat16 g_attl[(size_t)NB * NHID * NL];

__device__ __forceinline__ float ex2(float x) {
    float y; asm("ex2.approx.f32 %0, %1;" : "=f"(y) : "f"(x)); return y;
}
__device__ __forceinline__ unsigned pckbf(float lo, float hi) {
    unsigned r; asm("cvt.rn.bf16x2.f32 %0, %1, %2;" : "=r"(r) : "f"(hi), "f"(lo)); return r;
}
__device__ __forceinline__ float bfrt(float x) {
    float r;
    asm("{.reg .b16 t; cvt.rn.bf16.f32 t, %1; cvt.f32.bf16 %0, t;}" : "=f"(r) : "f"(x));
    return r;
}
__device__ __forceinline__ void cpa16(unsigned s, const void* g) {
    asm volatile("cp.async.cg.shared.global [%0], [%1], 16;" :: "r"(s), "l"(g));
}
#define CPCOMMIT() asm volatile("cp.async.commit_group;")
#define CPWAIT(n)  asm volatile("cp.async.wait_group %0;" :: "n"(n))

#define LDSMX4(R0,R1,R2,R3,A) \
    asm volatile("ldmatrix.sync.aligned.m8n8.x4.shared.b16 {%0,%1,%2,%3}, [%4];" \
        : "=r"(R0),"=r"(R1),"=r"(R2),"=r"(R3) : "r"(A))
#define LDSMX4T(R0,R1,R2,R3,A) \
    asm volatile("ldmatrix.sync.aligned.m8n8.x4.trans.shared.b16 {%0,%1,%2,%3}, [%4];" \
        : "=r"(R0),"=r"(R1),"=r"(R2),"=r"(R3) : "r"(A))
#define MMABF(C,A0,A1,A2,A3,B0,B1) \
    asm volatile("mma.sync.aligned.m16n8k16.row.col.f32.bf16.bf16.f32 " \
        "{%0,%1,%2,%3},{%4,%5,%6,%7},{%8,%9},{%0,%1,%2,%3};" \
        : "+f"(C[0]),"+f"(C[1]),"+f"(C[2]),"+f"(C[3]) \
        : "r"(A0),"r"(A1),"r"(A2),"r"(A3),"r"(B0),"r"(B1))

// ---------------------------------------------------------------------------
// fp32 -> bf16 hi/lo split passes
// ---------------------------------------------------------------------------
__global__ void cvt_split(const float4* __restrict__ src,
                          uint2* __restrict__ h, uint2* __restrict__ l)
{
    int i = blockIdx.x * blockDim.x + threadIdx.x;
    float4 f = src[i];
    uint2 hv, lv;
    hv.x = pckbf(f.x, f.y);
    hv.y = pckbf(f.z, f.w);
    lv.x = pckbf(f.x - bfrt(f.x), f.y - bfrt(f.y));
    lv.y = pckbf(f.z - bfrt(f.z), f.w - bfrt(f.w));
    h[i] = hv; l[i] = lv;
}

__global__ void cvt_splitT(const float* __restrict__ w,
                           __nv_bfloat16* __restrict__ ht,
                           __nv_bfloat16* __restrict__ lt, int M, int C)
{
    int idx = blockIdx.x * blockDim.x + threadIdx.x;
    int m = idx / C, c = idx % C;
    float v = w[idx];
    float hi = bfrt(v);
    ht[(size_t)c * M + m] = __float2bfloat16(hi);
    lt[(size_t)c * M + m] = __float2bfloat16(v - hi);
}

// ---------------------------------------------------------------------------
// bf16 split-MMA GEMM, 3-stage cp.async pipeline.
// Y[b][m][n] = sum_k A[k][m] * B[b][k][n] (+bias). Block 128x128, ktile 32.
// ---------------------------------------------------------------------------
#define GSTG 34816   // bytes per stage: 4 arrays x 32 x 136 x 2B

template<int M, int K, bool HAS_BIAS, bool SPLIT_OUT>
__global__ __launch_bounds__(256) void gemm_bf16(
    const __nv_bfloat16* __restrict__ Ah_g, const __nv_bfloat16* __restrict__ Al_g,
    const __nv_bfloat16* __restrict__ Bh_g, const __nv_bfloat16* __restrict__ Bl_g,
    const float* __restrict__ bias,
    __nv_bfloat16* __restrict__ Yh, __nv_bfloat16* __restrict__ Yl,
    float* __restrict__ Yf)
{
    extern __shared__ __align__(16) unsigned char smg[];
    const int NT = K / 32;

    const int b  = blockIdx.z;
    const int m0 = blockIdx.y * 128;
    const int n0 = blockIdx.x * 128;

    const int tid  = threadIdx.x;
    const int lane = tid & 31;
    const int warp = tid >> 5;
    const int wm   = warp >> 2;
    const int wn   = warp & 3;

    unsigned sb = (unsigned)__cvta_generic_to_shared(smg);

    const unsigned offA = ((((lane >> 4) & 1) * 8 + (lane & 7)) * 272)
                        + (wm * 64 + ((lane >> 3) & 1) * 8) * 2;
    const unsigned offB = ((((lane >> 3) & 1) * 8 + (lane & 7)) * 272)
                        + (wn * 32 + ((lane >> 4) & 1) * 8) * 2;

    // per-thread load coords (32 rows x 16 chunks, 2 chunks/thread/array)
    const int r0c = tid >> 4, c0c = (tid & 15) * 8;
    const int r1c = (tid + 256) >> 4, c1c = ((tid + 256) & 15) * 8;

    float acc[4][4][4];
    #pragma unroll
    for (int i = 0; i < 4; i++)
        #pragma unroll
        for (int j = 0; j < 4; j++)
            #pragma unroll
            for (int t = 0; t < 4; t++) acc[i][j][t] = 0.0f;

    auto issue = [&](int kt, int st) {
        unsigned base = sb + st * GSTG;
        int k0 = kt * 32;
        {
            size_t ga = (size_t)(k0 + r0c) * M + m0 + c0c;
            size_t gb = ((size_t)b * K + k0 + r0c) * NL + n0 + c0c;
            unsigned so = r0c * 272 + c0c * 2;
            cpa16(base + so,                 Ah_g + ga);
            cpa16(base + 8704 + so,          Al_g + ga);
            cpa16(base + 17408 + so,         Bh_g + gb);
            cpa16(base + 26112 + so,         Bl_g + gb);
        }
        {
            size_t ga = (size_t)(k0 + r1c) * M + m0 + c1c;
            size_t gb = ((size_t)b * K + k0 + r1c) * NL + n0 + c1c;
            unsigned so = r1c * 272 + c1c * 2;
            cpa16(base + so,                 Ah_g + ga);
            cpa16(base + 8704 + so,          Al_g + ga);
            cpa16(base + 17408 + so,         Bh_g + gb);
            cpa16(base + 26112 + so,         Bl_g + gb);
        }
    };

    issue(0, 0); CPCOMMIT();
    issue(1, 1); CPCOMMIT();

    for (int kt = 0; kt < NT; kt++) {
        CPWAIT(1);
        __syncthreads();
        if (kt + 2 < NT) issue(kt + 2, (kt + 2) % 3);
        CPCOMMIT();

        unsigned base = sb + (kt % 3) * GSTG;
        const unsigned SAH = base, SAL = base + 8704,
                       SBH = base + 17408, SBL = base + 26112;

        #pragma unroll
        for (int kc = 0; kc < 2; kc++) {
            unsigned kb = kc * 16 * 272;
            unsigned bh[2][4], bl[2][4];
            LDSMX4T(bh[0][0], bh[0][1], bh[0][2], bh[0][3], SBH + offB + kb);
            LDSMX4T(bh[1][0], bh[1][1], bh[1][2], bh[1][3], SBH + offB + kb + 32);
            LDSMX4T(bl[0][0], bl[0][1], bl[0][2], bl[0][3], SBL + offB + kb);
            LDSMX4T(bl[1][0], bl[1][1], bl[1][2], bl[1][3], SBL + offB + kb + 32);
            #pragma unroll
            for (int mf = 0; mf < 4; mf++) {
                unsigned ah0,ah1,ah2,ah3, al0,al1,al2,al3;
                LDSMX4T(ah0,ah1,ah2,ah3, SAH + offA + kb + mf * 32);
                LDSMX4T(al0,al1,al2,al3, SAL + offA + kb + mf * 32);
                #pragma unroll
                for (int g = 0; g < 4; g++) {
                    unsigned b0 = bh[g >> 1][(g & 1) * 2];
                    unsigned b1 = bh[g >> 1][(g & 1) * 2 + 1];
                    unsigned c0 = bl[g >> 1][(g & 1) * 2];
                    unsigned c1 = bl[g >> 1][(g & 1) * 2 + 1];
                    MMABF(acc[mf][g], ah0,ah1,ah2,ah3, b0,b1);
                    MMABF(acc[mf][g], ah0,ah1,ah2,ah3, c0,c1);
                    MMABF(acc[mf][g], al0,al1,al2,al3, b0,b1);
                }
            }
        }
    }

    // ---- epilogue ----
    const int r0 = lane >> 2;
    const int cp = (lane & 3) * 2;
    #pragma unroll
    for (int mf = 0; mf < 4; mf++) {
        int ml = wm * 64 + mf * 16 + r0;
        float bv0 = 0.0f, bv1 = 0.0f;
        if (HAS_BIAS) { bv0 = bias[m0 + ml]; bv1 = bias[m0 + ml + 8]; }
        #pragma unroll
        for (int g = 0; g < 4; g++) {
            int n = n0 + wn * 32 + g * 8 + cp;
            float* c = acc[mf][g];
            size_t a0 = ((size_t)b * M + m0 + ml) * NL + n;
            size_t a1 = a0 + (size_t)8 * NL;
            if (SPLIT_OUT) {
                *(unsigned*)(Yh + a0) = pckbf(c[0], c[1]);
                *(unsigned*)(Yl + a0) = pckbf(c[0] - bfrt(c[0]), c[1] - bfrt(c[1]));
                *(unsigned*)(Yh + a1) = pckbf(c[2], c[3]);
                *(unsigned*)(Yl + a1) = pckbf(c[2] - bfrt(c[2]), c[3] - bfrt(c[3]));
            } else {
                *(float2*)(Yf + a0) = make_float2(c[0] + bv0, c[1] + bv0);
                *(float2*)(Yf + a1) = make_float2(c[2] + bv1, c[3] + bv1);
            }
        }
    }
}

// ---------------------------------------------------------------------------
// Flash attention: BM=128 queries (8 warps x 16 rows), BN=64 keys,
// 2-stage cp.async K/V pipeline, bf16 3-MMA split, pre-split hi/lo I/O.
// smem: Q hi/lo 2x17408 + 2 stages x 36864 = 108544 B.
// ---------------------------------------------------------------------------
#define ASTG 36864

__global__ __launch_bounds__(256) void attn_kernel(
    const __nv_bfloat16* __restrict__ qkvh, const __nv_bfloat16* __restrict__ qkvl,
    __nv_bfloat16* __restrict__ atth, __nv_bfloat16* __restrict__ attl)
{
    extern __shared__ __align__(16) unsigned char sma[];

    const int tid  = threadIdx.x;
    const int lane = tid & 31;
    const int warp = tid >> 5;
    const int i0 = blockIdx.x * 128;
    const int h  = blockIdx.y;
    const int b  = blockIdx.z;

    const size_t base = ((size_t)b * NOQKV + h * ND) * NL;
    const __nv_bfloat16* qph = qkvh + base;
    const __nv_bfloat16* qpl = qkvl + base;
    const __nv_bfloat16* kph = qph + (size_t)NHID * NL;
    const __nv_bfloat16* kpl = qpl + (size_t)NHID * NL;
    const __nv_bfloat16* vph = qph + (size_t)2 * NHID * NL;
    const __nv_bfloat16* vpl = qpl + (size_t)2 * NHID * NL;

    unsigned sb = (unsigned)__cvta_generic_to_shared(sma);
    const unsigned QH = sb, QL = sb + 17408, KV0 = sb + 34816;

    // ldmatrix per-lane offsets
    const unsigned offQ = (((lane >> 4) & 1) * 8 + (lane & 7)) * 272
                        + (warp * 16 + ((lane >> 3) & 1) * 8) * 2;
    const unsigned offK = (((lane >> 3) & 1) * 8 + (lane & 7)) * 144
                        + (((lane >> 4) & 1) * 8) * 2;
    const unsigned offV = (((lane >> 4) & 1) * 8 + (lane & 7)) * 144
                        + (((lane >> 3) & 1) * 8) * 2;

    const float SC = 0.125f * 1.44269504f;

    // K/V per-thread load coords: 64 rows x 8 chunks = 512 chunks/array,
    // 2 chunks per thread (FIX for R6: was 1 chunk -> half tile unwritten)
    auto issueKV = [&](int j0, int st) {
        unsigned kb = KV0 + st * ASTG;
        #pragma unroll
        for (int p = 0; p < 2; p++) {
            int q   = tid + p * 256;
            int row = q >> 3;              // 0..63
            int col = (q & 7) * 8;         // 0..56
            unsigned so = row * 144 + col * 2;
            size_t g = (size_t)row * NL + j0 + col;
            cpa16(kb + so,          kph + g);
            cpa16(kb + 9216 + so,   kpl + g);
            cpa16(kb + 18432 + so,  vph + g);
            cpa16(kb + 27648 + so,  vpl + g);
        }
    };

    // Q loads: 64 rows x 16 chunks per tensor, 4 chunks/thread
    {
        #pragma unroll
        for (int p = 0; p < 4; p++) {
            int q = tid + p * 256;
            int r = q >> 4, c16 = (q & 15) * 8;
            unsigned so = r * 272 + c16 * 2;
            size_t g = (size_t)r * NL + i0 + c16;
            cpa16(QH + so, qph + g);
            cpa16(QL + so, qpl + g);
        }
        issueKV(0, 0);
        CPCOMMIT();
    }

    float o[8][4];
    #pragma unroll
    for (int t = 0; t < 8; t++) { o[t][0]=0; o[t][1]=0; o[t][2]=0; o[t][3]=0; }
    float m0 = -1e30f, m1 = -1e30f, l0 = 0.0f, l1 = 0.0f;

    for (int jt = 0; jt < 32; jt++) {
        if (jt + 1 < 32) issueKV((jt + 1) * 64, (jt + 1) & 1);
        CPCOMMIT();
        CPWAIT(1);
        __syncthreads();

        unsigned kb = KV0 + (jt & 1) * ASTG;
        const unsigned KH = kb, KL = kb + 9216, VH = kb + 18432, VL = kb + 27648;

        // ---- S = Q K^T (m16 x n64 per warp), 3-MMA split ----
        float s[8][4];
        #pragma unroll
        for (int t = 0; t < 8; t++) { s[t][0]=0; s[t][1]=0; s[t][2]=0; s[t][3]=0; }

        #pragma unroll
        for (int kc = 0; kc < 4; kc++) {
            unsigned kcq = kc * 16 * 272;
            unsigned kck = kc * 16 * 144;
            unsigned qa0,qa1,qa2,qa3, qb0,qb1,qb2,qb3;
            LDSMX4T(qa0,qa1,qa2,qa3, QH + offQ + kcq);
            LDSMX4T(qb0,qb1,qb2,qb3, QL + offQ + kcq);
            #pragma unroll
            for (int p = 0; p < 4; p++) {
                unsigned nb = p * 32;
                unsigned h0,h1,h2,h3, e0,e1,e2,e3;
                LDSMX4T(h0,h1,h2,h3, KH + offK + kck + nb);
                LDSMX4T(e0,e1,e2,e3, KL + offK + kck + nb);
                MMABF(s[2*p],   qa0,qa1,qa2,qa3, h0,h1);
                MMABF(s[2*p],   qa0,qa1,qa2,qa3, e0,e1);
                MMABF(s[2*p],   qb0,qb1,qb2,qb3, h0,h1);
                MMABF(s[2*p+1], qa0,qa1,qa2,qa3, h2,h3);
                MMABF(s[2*p+1], qa0,qa1,qa2,qa3, e2,e3);
                MMABF(s[2*p+1], qb0,qb1,qb2,qb3, h2,h3);
            }
        }

        #pragma unroll
        for (int t = 0; t < 8; t++) {
            s[t][0] *= SC; s[t][1] *= SC; s[t][2] *= SC; s[t][3] *= SC;
        }

        // ---- online softmax ----
        float mx0 = -1e30f, mx1 = -1e30f;
        #pragma unroll
        for (int t = 0; t < 8; t++) {
            mx0 = fmaxf(mx0, fmaxf(s[t][0], s[t][1]));
            mx1 = fmaxf(mx1, fmaxf(s[t][2], s[t][3]));
        }
        mx0 = fmaxf(mx0, __shfl_xor_sync(0xffffffffu, mx0, 1));
        mx0 = fmaxf(mx0, __shfl_xor_sync(0xffffffffu, mx0, 2));
        mx1 = fmaxf(mx1, __shfl_xor_sync(0xffffffffu, mx1, 1));
        mx1 = fmaxf(mx1, __shfl_xor_sync(0xffffffffu, mx1, 2));
        float mn0 = fmaxf(m0, mx0), mn1 = fmaxf(m1, mx1);
        float c0 = ex2(m0 - mn0),   c1 = ex2(m1 - mn1);
        m0 = mn0; m1 = mn1;

        float rs0 = 0.0f, rs1 = 0.0f;
        #pragma unroll
        for (int t = 0; t < 8; t++) {
            s[t][0] = ex2(s[t][0] - mn0);
            s[t][1] = ex2(s[t][1] - mn0);
            s[t][2] = ex2(s[t][2] - mn1);
            s[t][3] = ex2(s[t][3] - mn1);
            rs0 += s[t][0] + s[t][1];
            rs1 += s[t][2] + s[t][3];
        }
        l0 = l0 * c0 + rs0;
        l1 = l1 * c1 + rs1;
        #pragma unroll
        for (int t = 0; t < 8; t++) {
            o[t][0] *= c0; o[t][1] *= c0; o[t][2] *= c1; o[t][3] *= c1;
        }

        // ---- P fragments (hi/lo) from S registers ----
        unsigned pah[4][4], pal[4][4];
        #pragma unroll
        for (int c = 0; c < 4; c++) {
            int A = 2 * c, B = 2 * c + 1;
            pah[c][0] = pckbf(s[A][0], s[A][1]);
            pah[c][1] = pckbf(s[A][2], s[A][3]);
            pah[c][2] = pckbf(s[B][0], s[B][1]);
            pah[c][3] = pckbf(s[B][2], s[B][3]);
            pal[c][0] = pckbf(s[A][0]-bfrt(s[A][0]), s[A][1]-bfrt(s[A][1]));
            pal[c][1] = pckbf(s[A][2]-bfrt(s[A][2]), s[A][3]-bfrt(s[A][3]));
            pal[c][2] = pckbf(s[B][0]-bfrt(s[B][0]), s[B][1]-bfrt(s[B][1]));
            pal[c][3] = pckbf(s[B][2]-bfrt(s[B][2]), s[B][3]-bfrt(s[B][3]));
        }

        // ---- O += P V ----
        #pragma unroll
        for (int c = 0; c < 4; c++) {
            unsigned jb = c * 32;
            #pragma unroll
            for (int p = 0; p < 4; p++) {
                unsigned db = p * 2304;
                unsigned h0,h1,h2,h3, e0,e1,e2,e3;
                LDSMX4(h0,h1,h2,h3, VH + offV + db + jb);
                LDSMX4(e0,e1,e2,e3, VL + offV + db + jb);
                MMABF(o[2*p],   pah[c][0],pah[c][1],pah[c][2],pah[c][3], h0,h1);
                MMABF(o[2*p],   pah[c][0],pah[c][1],pah[c][2],pah[c][3], e0,e1);
                MMABF(o[2*p],   pal[c][0],pal[c][1],pal[c][2],pal[c][3], h0,h1);
                MMABF(o[2*p+1], pah[c][0],pah[c][1],pah[c][2],pah[c][3], h2,h3);
                MMABF(o[2*p+1], pah[c][0],pah[c][1],pah[c][2],pah[c][3], e2,e3);
                MMABF(o[2*p+1], pal[c][0],pal[c][1],pal[c][2],pal[c][3], h2,h3);
            }
        }
        __syncthreads();
    }

    // ---- finalize ----
    l0 += __shfl_xor_sync(0xffffffffu, l0, 1);
    l0 += __shfl_xor_sync(0xffffffffu, l0, 2);
    l1 += __shfl_xor_sync(0xffffffffu, l1, 1);
    l1 += __shfl_xor_sync(0xffffffffu, l1, 2);
    float inv0 = __fdividef(1.0f, l0);
    float inv1 = __fdividef(1.0f, l1);

    const size_t ob = ((size_t)b * NHID + h * ND) * NL;
    int ig = i0 + warp * 16 + (lane >> 2);
    #pragma unroll
    for (int dt = 0; dt < 8; dt++) {
        int d = dt * 8 + (lane & 3) * 2;
        float v0 = o[dt][0] * inv0, v1 = o[dt][1] * inv0;
        float v2 = o[dt][2] * inv1, v3 = o[dt][3] * inv1;
        size_t a0 = ob + (size_t)d * NL + ig;
        size_t a1 = ob + (size_t)(d + 1) * NL + ig;
        atth[a0]     = __float2bfloat16(v0);
        attl[a0]     = __float2bfloat16(v0 - bfrt(v0));
        atth[a1]     = __float2bfloat16(v1);
        attl[a1]     = __float2bfloat16(v1 - bfrt(v1));
        atth[a0 + 8] = __float2bfloat16(v2);
        attl[a0 + 8] = __float2bfloat16(v2 - bfrt(v2));
        atth[a1 + 8] = __float2bfloat16(v3);
        attl[a1 + 8] = __float2bfloat16(v3 - bfrt(v3));
    }
}

// ---------------------------------------------------------------------------
extern "C" void kernel_launch(void* const* d_in, const int* in_sizes, int n_in,
                              void* d_out, int out_size)
{
    const float* x     = (const float*)d_in[0];
    const float* w_qkv = (const float*)d_in[1];
    const float* w_out = (const float*)d_in[2];
    const float* b_out = (const float*)d_in[3];
    float* out = (float*)d_out;

    __nv_bfloat16 *xh, *xl, *wqh, *wql, *woh, *wol, *qkvh, *qkvl, *atth, *attl;
    cudaGetSymbolAddress((void**)&xh,   g_xh);
    cudaGetSymbolAddress((void**)&xl,   g_xl);
    cudaGetSymbolAddress((void**)&wqh,  g_wqh);
    cudaGetSymbolAddress((void**)&wql,  g_wql);
    cudaGetSymbolAddress((void**)&woh,  g_woh);
    cudaGetSymbolAddress((void**)&wol,  g_wol);
    cudaGetSymbolAddress((void**)&qkvh, g_qkvh);
    cudaGetSymbolAddress((void**)&qkvl, g_qkvl);
    cudaGetSymbolAddress((void**)&atth, g_atth);
    cudaGetSymbolAddress((void**)&attl, g_attl);

    // 0) split inputs/weights
    cvt_split<<<(NB * NC * NL / 4) / 256, 256>>>(
        (const float4*)x, (uint2*)xh, (uint2*)xl);
    cvt_splitT<<<(NOQKV * NC) / 256, 256>>>(w_qkv, wqh, wql, NOQKV, NC);
    cvt_splitT<<<(NC * NHID) / 256, 256>>>(w_out, woh, wol, NC, NHID);

    const int gsmem = 3 * GSTG;            // 104448
    const int asmem = 34816 + 2 * ASTG;    // 108544

    // 1) QKV projection
    cudaFuncSetAttribute(gemm_bf16<NOQKV, NC, false, true>,
                         cudaFuncAttributeMaxDynamicSharedMemorySize, gsmem);
    gemm_bf16<NOQKV, NC, false, true>
        <<<dim3(NL / 128, NOQKV / 128, NB), 256, gsmem>>>(
            wqh, wql, xh, xl, nullptr, qkvh, qkvl, nullptr);

    // 2) Attention
    cudaFuncSetAttribute(attn_kernel,
                         cudaFuncAttributeMaxDynamicSharedMemorySize, asmem);
    attn_kernel<<<dim3(NL / 128, NH, NB), 256, asmem>>>(qkvh, qkvl, atth, attl);

    // 3) Output projection + bias
    cudaFuncSetAttribute(gemm_bf16<NC, NHID, true, false>,
                         cudaFuncAttributeMaxDynamicSharedMemorySize, gsmem);
    gemm_bf16<NC, NHID, true, false>
        <<<dim3(NL / 128, NC / 128, NB), 256, gsmem>>>(
            woh, wol, atth, attl, b_out, nullptr, nullptr, out);
}

// round 8
// speedup vs baseline: 4.3165x; 1.0438x over previous
#include <cuda_runtime.h>
#include <cuda_bf16.h>

#define NB    8
#define NC    512
#define NL    2048
#define NH    8
#define ND    64
#define NHID  512
#define NOQKV 1536

// ---------------- device-global scratch (allocation-free) ----------------
__device__ __nv_bfloat16 g_xh[(size_t)NB * NC * NL];
__device__ __nv_bfloat16 g_xl[(size_t)NB * NC * NL];
__device__ __nv_bfloat16 g_wqh[(size_t)NC * NOQKV];    // [c][m] transposed
__device__ __nv_bfloat16 g_wql[(size_t)NC * NOQKV];
__device__ __nv_bfloat16 g_woh[(size_t)NHID * NC];     // [c][m] transposed
__device__ __nv_bfloat16 g_wol[(size_t)NHID * NC];
__device__ __nv_bfloat16 g_qkvh[(size_t)NB * NOQKV * NL];
__device__ __nv_bfloat16 g_qkvl[(size_t)NB * NOQKV * NL];
__device__ __nv_bfloat16 g_atth[(size_t)NB * NHID * NL];
__device__ __nv_bfloat16 g_attl[(size_t)NB * NHID * NL];

__device__ __forceinline__ float ex2(float x) {
    float y; asm("ex2.approx.f32 %0, %1;" : "=f"(y) : "f"(x)); return y;
}
__device__ __forceinline__ unsigned pckbf(float lo, float hi) {
    unsigned r; asm("cvt.rn.bf16x2.f32 %0, %1, %2;" : "=r"(r) : "f"(hi), "f"(lo)); return r;
}
__device__ __forceinline__ float bfrt(float x) {
    float r;
    asm("{.reg .b16 t; cvt.rn.bf16.f32 t, %1; cvt.f32.bf16 %0, t;}" : "=f"(r) : "f"(x));
    return r;
}
__device__ __forceinline__ void cpa16(unsigned s, const void* g) {
    asm volatile("cp.async.cg.shared.global [%0], [%1], 16;" :: "r"(s), "l"(g));
}
#define CPCOMMIT() asm volatile("cp.async.commit_group;")
#define CPWAIT(n)  asm volatile("cp.async.wait_group %0;" :: "n"(n))

#define LDSMX4(R0,R1,R2,R3,A) \
    asm volatile("ldmatrix.sync.aligned.m8n8.x4.shared.b16 {%0,%1,%2,%3}, [%4];" \
        : "=r"(R0),"=r"(R1),"=r"(R2),"=r"(R3) : "r"(A))
#define LDSMX4T(R0,R1,R2,R3,A) \
    asm volatile("ldmatrix.sync.aligned.m8n8.x4.trans.shared.b16 {%0,%1,%2,%3}, [%4];" \
        : "=r"(R0),"=r"(R1),"=r"(R2),"=r"(R3) : "r"(A))
#define MMABF(C,A0,A1,A2,A3,B0,B1) \
    asm volatile("mma.sync.aligned.m16n8k16.row.col.f32.bf16.bf16.f32 " \
        "{%0,%1,%2,%3},{%4,%5,%6,%7},{%8,%9},{%0,%1,%2,%3};" \
        : "+f"(C[0]),"+f"(C[1]),"+f"(C[2]),"+f"(C[3]) \
        : "r"(A0),"r"(A1),"r"(A2),"r"(A3),"r"(B0),"r"(B1))

// ---------------------------------------------------------------------------
// fp32 -> bf16 hi/lo split passes
// ---------------------------------------------------------------------------
__global__ void cvt_split(const float4* __restrict__ src,
                          uint2* __restrict__ h, uint2* __restrict__ l)
{
    int i = blockIdx.x * blockDim.x + threadIdx.x;
    float4 f = src[i];
    uint2 hv, lv;
    hv.x = pckbf(f.x, f.y);
    hv.y = pckbf(f.z, f.w);
    lv.x = pckbf(f.x - bfrt(f.x), f.y - bfrt(f.y));
    lv.y = pckbf(f.z - bfrt(f.z), f.w - bfrt(f.w));
    h[i] = hv; l[i] = lv;
}

__global__ void cvt_splitT(const float* __restrict__ w,
                           __nv_bfloat16* __restrict__ ht,
                           __nv_bfloat16* __restrict__ lt, int M, int C)
{
    int idx = blockIdx.x * blockDim.x + threadIdx.x;
    int m = idx / C, c = idx % C;
    float v = w[idx];
    float hi = bfrt(v);
    ht[(size_t)c * M + m] = __float2bfloat16(hi);
    lt[(size_t)c * M + m] = __float2bfloat16(v - hi);
}

// ---------------------------------------------------------------------------
// bf16 split-MMA GEMM, 3-stage cp.async pipeline.
// Block 128x128, ktile 32, 128 threads = 4 warps in 2x2 grid, 64x64 per warp.
// ---------------------------------------------------------------------------
#define GSTG 34816   // bytes per stage: 4 arrays x 32 x 136 x 2B

template<int M, int K, bool HAS_BIAS, bool SPLIT_OUT>
__global__ __launch_bounds__(128) void gemm_bf16(
    const __nv_bfloat16* __restrict__ Ah_g, const __nv_bfloat16* __restrict__ Al_g,
    const __nv_bfloat16* __restrict__ Bh_g, const __nv_bfloat16* __restrict__ Bl_g,
    const float* __restrict__ bias,
    __nv_bfloat16* __restrict__ Yh, __nv_bfloat16* __restrict__ Yl,
    float* __restrict__ Yf)
{
    extern __shared__ __align__(16) unsigned char smg[];
    const int NT = K / 32;

    const int b  = blockIdx.z;
    const int m0 = blockIdx.y * 128;
    const int n0 = blockIdx.x * 128;

    const int tid  = threadIdx.x;
    const int lane = tid & 31;
    const int warp = tid >> 5;      // 0..3
    const int wm   = warp >> 1;     // m offset wm*64
    const int wn   = warp & 1;      // n offset wn*64

    unsigned sb = (unsigned)__cvta_generic_to_shared(smg);

    const unsigned offA = ((((lane >> 4) & 1) * 8 + (lane & 7)) * 272)
                        + (wm * 64 + ((lane >> 3) & 1) * 8) * 2;
    const unsigned offB = ((((lane >> 3) & 1) * 8 + (lane & 7)) * 272)
                        + (wn * 64 + ((lane >> 4) & 1) * 8) * 2;

    float acc[4][8][4];
    #pragma unroll
    for (int i = 0; i < 4; i++)
        #pragma unroll
        for (int j = 0; j < 8; j++)
            #pragma unroll
            for (int t = 0; t < 4; t++) acc[i][j][t] = 0.0f;

    // loads: 4 arrays x (32 rows x 16 chunks); 4 chunks/thread/array
    auto issue = [&](int kt, int st) {
        unsigned base = sb + st * GSTG;
        int k0 = kt * 32;
        #pragma unroll
        for (int p = 0; p < 4; p++) {
            int q   = tid + p * 128;
            int row = q >> 4;
            int c8  = (q & 15) * 8;
            size_t ga = (size_t)(k0 + row) * M + m0 + c8;
            size_t gb = ((size_t)b * K + k0 + row) * NL + n0 + c8;
            unsigned so = row * 272 + c8 * 2;
            cpa16(base + so,          Ah_g + ga);
            cpa16(base + 8704 + so,   Al_g + ga);
            cpa16(base + 17408 + so,  Bh_g + gb);
            cpa16(base + 26112 + so,  Bl_g + gb);
        }
    };

    issue(0, 0); CPCOMMIT();
    issue(1, 1); CPCOMMIT();

    for (int kt = 0; kt < NT; kt++) {
        CPWAIT(1);
        __syncthreads();
        if (kt + 2 < NT) issue(kt + 2, (kt + 2) % 3);
        CPCOMMIT();

        unsigned base = sb + (kt % 3) * GSTG;
        const unsigned SAH = base, SAL = base + 8704,
                       SBH = base + 17408, SBL = base + 26112;

        #pragma unroll
        for (int kc = 0; kc < 2; kc++) {
            unsigned kb = kc * 16 * 272;
            unsigned bh[4][4], bl[4][4];
            #pragma unroll
            for (int ng = 0; ng < 4; ng++) {
                LDSMX4T(bh[ng][0], bh[ng][1], bh[ng][2], bh[ng][3],
                        SBH + offB + kb + ng * 32);
                LDSMX4T(bl[ng][0], bl[ng][1], bl[ng][2], bl[ng][3],
                        SBL + offB + kb + ng * 32);
            }
            #pragma unroll
            for (int mf = 0; mf < 4; mf++) {
                unsigned ah0,ah1,ah2,ah3, al0,al1,al2,al3;
                LDSMX4T(ah0,ah1,ah2,ah3, SAH + offA + kb + mf * 32);
                LDSMX4T(al0,al1,al2,al3, SAL + offA + kb + mf * 32);
                #pragma unroll
                for (int ng = 0; ng < 4; ng++) {
                    MMABF(acc[mf][2*ng],   ah0,ah1,ah2,ah3, bh[ng][0],bh[ng][1]);
                    MMABF(acc[mf][2*ng],   ah0,ah1,ah2,ah3, bl[ng][0],bl[ng][1]);
                    MMABF(acc[mf][2*ng],   al0,al1,al2,al3, bh[ng][0],bh[ng][1]);
                    MMABF(acc[mf][2*ng+1], ah0,ah1,ah2,ah3, bh[ng][2],bh[ng][3]);
                    MMABF(acc[mf][2*ng+1], ah0,ah1,ah2,ah3, bl[ng][2],bl[ng][3]);
                    MMABF(acc[mf][2*ng+1], al0,al1,al2,al3, bh[ng][2],bh[ng][3]);
                }
            }
        }
    }

    // ---- epilogue ----
    const int r0 = lane >> 2;
    const int cp = (lane & 3) * 2;
    #pragma unroll
    for (int mf = 0; mf < 4; mf++) {
        int ml = m0 + wm * 64 + mf * 16 + r0;
        float bv0 = 0.0f, bv1 = 0.0f;
        if (HAS_BIAS) { bv0 = bias[ml]; bv1 = bias[ml + 8]; }
        #pragma unroll
        for (int g = 0; g < 8; g++) {
            int n = n0 + wn * 64 + (g >> 1) * 16 + (g & 1) * 8 + cp;
            float* c = acc[mf][g];
            size_t a0 = ((size_t)b * M + ml) * NL + n;
            size_t a1 = a0 + (size_t)8 * NL;
            if (SPLIT_OUT) {
                *(unsigned*)(Yh + a0) = pckbf(c[0], c[1]);
                *(unsigned*)(Yl + a0) = pckbf(c[0] - bfrt(c[0]), c[1] - bfrt(c[1]));
                *(unsigned*)(Yh + a1) = pckbf(c[2], c[3]);
                *(unsigned*)(Yl + a1) = pckbf(c[2] - bfrt(c[2]), c[3] - bfrt(c[3]));
            } else {
                *(float2*)(Yf + a0) = make_float2(c[0] + bv0, c[1] + bv0);
                *(float2*)(Yf + a1) = make_float2(c[2] + bv1, c[3] + bv1);
            }
        }
    }
}

// ---------------------------------------------------------------------------
// Flash attention: BM=128 queries, 4 warps x m32 rows each, BN=64 keys,
// 2-stage cp.async K/V pipeline, bf16 3-MMA split, pre-split hi/lo I/O.
// ---------------------------------------------------------------------------
#define ASTG 36864

__global__ __launch_bounds__(128) void attn_kernel(
    const __nv_bfloat16* __restrict__ qkvh, const __nv_bfloat16* __restrict__ qkvl,
    __nv_bfloat16* __restrict__ atth, __nv_bfloat16* __restrict__ attl)
{
    extern __shared__ __align__(16) unsigned char sma[];

    const int tid  = threadIdx.x;
    const int lane = tid & 31;
    const int warp = tid >> 5;     // 0..3, rows warp*32..warp*32+31
    const int i0 = blockIdx.x * 128;
    const int h  = blockIdx.y;
    const int b  = blockIdx.z;

    const size_t base = ((size_t)b * NOQKV + h * ND) * NL;
    const __nv_bfloat16* qph = qkvh + base;
    const __nv_bfloat16* qpl = qkvl + base;
    const __nv_bfloat16* kph = qph + (size_t)NHID * NL;
    const __nv_bfloat16* kpl = qpl + (size_t)NHID * NL;
    const __nv_bfloat16* vph = qph + (size_t)2 * NHID * NL;
    const __nv_bfloat16* vpl = qpl + (size_t)2 * NHID * NL;

    unsigned sb = (unsigned)__cvta_generic_to_shared(sma);
    const unsigned QH = sb, QL = sb + 17408, KV0 = sb + 34816;

    // ldmatrix per-lane offsets. Q rows 272B; K/V rows 144B.
    const unsigned offQ = (((lane >> 4) & 1) * 8 + (lane & 7)) * 272
                        + (warp * 32 + ((lane >> 3) & 1) * 8) * 2;  // +mb*32 bytes
    const unsigned offK = (((lane >> 3) & 1) * 8 + (lane & 7)) * 144
                        + (((lane >> 4) & 1) * 8) * 2;
    const unsigned offV = (((lane >> 4) & 1) * 8 + (lane & 7)) * 144
                        + (((lane >> 3) & 1) * 8) * 2;

    const float SC = 0.125f * 1.44269504f;

    // K/V: 4 arrays x (64 rows x 8 chunks) = 2048 chunks; 16/thread
    auto issueKV = [&](int j0, int st) {
        unsigned kb = KV0 + st * ASTG;
        #pragma unroll
        for (int p = 0; p < 4; p++) {
            int q   = tid + p * 128;
            int row = q >> 3;
            int col = (q & 7) * 8;
            unsigned so = row * 144 + col * 2;
            size_t g = (size_t)row * NL + j0 + col;
            cpa16(kb + so,          kph + g);
            cpa16(kb + 9216 + so,   kpl + g);
            cpa16(kb + 18432 + so,  vph + g);
            cpa16(kb + 27648 + so,  vpl + g);
        }
    };

    // Q: 2 arrays x (64 rows x 16 chunks); 8 chunks/thread/array
    {
        #pragma unroll
        for (int p = 0; p < 8; p++) {
            int q = tid + p * 128;
            int r = q >> 4, c16 = (q & 15) * 8;
            unsigned so = r * 272 + c16 * 2;
            size_t g = (size_t)r * NL + i0 + c16;
            cpa16(QH + so, qph + g);
            cpa16(QL + so, qpl + g);
        }
        issueKV(0, 0);
        CPCOMMIT();
    }

    float o[2][8][4];
    float mm[2][2], ll[2][2];
    #pragma unroll
    for (int mb = 0; mb < 2; mb++) {
        mm[mb][0] = -1e30f; mm[mb][1] = -1e30f;
        ll[mb][0] = 0.0f;   ll[mb][1] = 0.0f;
        #pragma unroll
        for (int t = 0; t < 8; t++)
            #pragma unroll
            for (int c = 0; c < 4; c++) o[mb][t][c] = 0.0f;
    }

    for (int jt = 0; jt < 32; jt++) {
        if (jt + 1 < 32) issueKV((jt + 1) * 64, (jt + 1) & 1);
        CPCOMMIT();
        CPWAIT(1);
        __syncthreads();

        unsigned kb = KV0 + (jt & 1) * ASTG;
        const unsigned KH = kb, KL = kb + 9216, VH = kb + 18432, VL = kb + 27648;

        // ---- S = Q K^T : m32 x n64 per warp, 3-MMA split ----
        float s[2][8][4];
        #pragma unroll
        for (int mb = 0; mb < 2; mb++)
            #pragma unroll
            for (int t = 0; t < 8; t++)
                #pragma unroll
                for (int c = 0; c < 4; c++) s[mb][t][c] = 0.0f;

        #pragma unroll
        for (int kc = 0; kc < 4; kc++) {
            unsigned kcq = kc * 16 * 272;
            unsigned kck = kc * 16 * 144;
            unsigned qa[2][4], qe[2][4];
            LDSMX4T(qa[0][0],qa[0][1],qa[0][2],qa[0][3], QH + offQ + kcq);
            LDSMX4T(qa[1][0],qa[1][1],qa[1][2],qa[1][3], QH + offQ + kcq + 32);
            LDSMX4T(qe[0][0],qe[0][1],qe[0][2],qe[0][3], QL + offQ + kcq);
            LDSMX4T(qe[1][0],qe[1][1],qe[1][2],qe[1][3], QL + offQ + kcq + 32);
            #pragma unroll
            for (int p = 0; p < 4; p++) {
                unsigned nb = p * 32;
                unsigned h0,h1,h2,h3, e0,e1,e2,e3;
                LDSMX4T(h0,h1,h2,h3, KH + offK + kck + nb);
                LDSMX4T(e0,e1,e2,e3, KL + offK + kck + nb);
                #pragma unroll
                for (int mb = 0; mb < 2; mb++) {
                    MMABF(s[mb][2*p],   qa[mb][0],qa[mb][1],qa[mb][2],qa[mb][3], h0,h1);
                    MMABF(s[mb][2*p],   qa[mb][0],qa[mb][1],qa[mb][2],qa[mb][3], e0,e1);
                    MMABF(s[mb][2*p],   qe[mb][0],qe[mb][1],qe[mb][2],qe[mb][3], h0,h1);
                    MMABF(s[mb][2*p+1], qa[mb][0],qa[mb][1],qa[mb][2],qa[mb][3], h2,h3);
                    MMABF(s[mb][2*p+1], qa[mb][0],qa[mb][1],qa[mb][2],qa[mb][3], e2,e3);
                    MMABF(s[mb][2*p+1], qe[mb][0],qe[mb][1],qe[mb][2],qe[mb][3], h2,h3);
                }
            }
        }

        // ---- online softmax + P fragments per mb ----
        unsigned pah[2][4][4], pal[2][4][4];
        #pragma unroll
        for (int mb = 0; mb < 2; mb++) {
            float mx0 = -1e30f, mx1 = -1e30f;
            #pragma unroll
            for (int t = 0; t < 8; t++) {
                s[mb][t][0] *= SC; s[mb][t][1] *= SC;
                s[mb][t][2] *= SC; s[mb][t][3] *= SC;
                mx0 = fmaxf(mx0, fmaxf(s[mb][t][0], s[mb][t][1]));
                mx1 = fmaxf(mx1, fmaxf(s[mb][t][2], s[mb][t][3]));
            }
            mx0 = fmaxf(mx0, __shfl_xor_sync(0xffffffffu, mx0, 1));
            mx0 = fmaxf(mx0, __shfl_xor_sync(0xffffffffu, mx0, 2));
            mx1 = fmaxf(mx1, __shfl_xor_sync(0xffffffffu, mx1, 1));
            mx1 = fmaxf(mx1, __shfl_xor_sync(0xffffffffu, mx1, 2));
            float mn0 = fmaxf(mm[mb][0], mx0), mn1 = fmaxf(mm[mb][1], mx1);
            float c0 = ex2(mm[mb][0] - mn0),   c1 = ex2(mm[mb][1] - mn1);
            mm[mb][0] = mn0; mm[mb][1] = mn1;

            float rs0 = 0.0f, rs1 = 0.0f;
            #pragma unroll
            for (int t = 0; t < 8; t++) {
                s[mb][t][0] = ex2(s[mb][t][0] - mn0);
                s[mb][t][1] = ex2(s[mb][t][1] - mn0);
                s[mb][t][2] = ex2(s[mb][t][2] - mn1);
                s[mb][t][3] = ex2(s[mb][t][3] - mn1);
                rs0 += s[mb][t][0] + s[mb][t][1];
                rs1 += s[mb][t][2] + s[mb][t][3];
            }
            ll[mb][0] = ll[mb][0] * c0 + rs0;
            ll[mb][1] = ll[mb][1] * c1 + rs1;
            #pragma unroll
            for (int t = 0; t < 8; t++) {
                o[mb][t][0] *= c0; o[mb][t][1] *= c0;
                o[mb][t][2] *= c1; o[mb][t][3] *= c1;
            }
            #pragma unroll
            for (int c = 0; c < 4; c++) {
                int A = 2 * c, B = 2 * c + 1;
                pah[mb][c][0] = pckbf(s[mb][A][0], s[mb][A][1]);
                pah[mb][c][1] = pckbf(s[mb][A][2], s[mb][A][3]);
                pah[mb][c][2] = pckbf(s[mb][B][0], s[mb][B][1]);
                pah[mb][c][3] = pckbf(s[mb][B][2], s[mb][B][3]);
                pal[mb][c][0] = pckbf(s[mb][A][0]-bfrt(s[mb][A][0]), s[mb][A][1]-bfrt(s[mb][A][1]));
                pal[mb][c][1] = pckbf(s[mb][A][2]-bfrt(s[mb][A][2]), s[mb][A][3]-bfrt(s[mb][A][3]));
                pal[mb][c][2] = pckbf(s[mb][B][0]-bfrt(s[mb][B][0]), s[mb][B][1]-bfrt(s[mb][B][1]));
                pal[mb][c][3] = pckbf(s[mb][B][2]-bfrt(s[mb][B][2]), s[mb][B][3]-bfrt(s[mb][B][3]));
            }
        }

        // ---- O += P V : shared V fragments across both mb ----
        #pragma unroll
        for (int c = 0; c < 4; c++) {
            unsigned jb = c * 32;
            #pragma unroll
            for (int p = 0; p < 4; p++) {
                unsigned db = p * 2304;
                unsigned h0,h1,h2,h3, e0,e1,e2,e3;
                LDSMX4(h0,h1,h2,h3, VH + offV + db + jb);
                LDSMX4(e0,e1,e2,e3, VL + offV + db + jb);
                #pragma unroll
                for (int mb = 0; mb < 2; mb++) {
                    MMABF(o[mb][2*p],   pah[mb][c][0],pah[mb][c][1],pah[mb][c][2],pah[mb][c][3], h0,h1);
                    MMABF(o[mb][2*p],   pah[mb][c][0],pah[mb][c][1],pah[mb][c][2],pah[mb][c][3], e0,e1);
                    MMABF(o[mb][2*p],   pal[mb][c][0],pal[mb][c][1],pal[mb][c][2],pal[mb][c][3], h0,h1);
                    MMABF(o[mb][2*p+1], pah[mb][c][0],pah[mb][c][1],pah[mb][c][2],pah[mb][c][3], h2,h3);
                    MMABF(o[mb][2*p+1], pah[mb][c][0],pah[mb][c][1],pah[mb][c][2],pah[mb][c][3], e2,e3);
                    MMABF(o[mb][2*p+1], pal[mb][c][0],pal[mb][c][1],pal[mb][c][2],pal[mb][c][3], h2,h3);
                }
            }
        }
        __syncthreads();
    }

    // ---- finalize ----
    const size_t ob = ((size_t)b * NHID + h * ND) * NL;
    #pragma unroll
    for (int mb = 0; mb < 2; mb++) {
        float l0 = ll[mb][0], l1 = ll[mb][1];
        l0 += __shfl_xor_sync(0xffffffffu, l0, 1);
        l0 += __shfl_xor_sync(0xffffffffu, l0, 2);
        l1 += __shfl_xor_sync(0xffffffffu, l1, 1);
        l1 += __shfl_xor_sync(0xffffffffu, l1, 2);
        float inv0 = __fdividef(1.0f, l0);
        float inv1 = __fdividef(1.0f, l1);

        int ig = i0 + warp * 32 + mb * 16 + (lane >> 2);
        #pragma unroll
        for (int dt = 0; dt < 8; dt++) {
            int d = dt * 8 + (lane & 3) * 2;
            float v0 = o[mb][dt][0] * inv0, v1 = o[mb][dt][1] * inv0;
            float v2 = o[mb][dt][2] * inv1, v3 = o[mb][dt][3] * inv1;
            size_t a0 = ob + (size_t)d * NL + ig;
            size_t a1 = ob + (size_t)(d + 1) * NL + ig;
            atth[a0]     = __float2bfloat16(v0);
            attl[a0]     = __float2bfloat16(v0 - bfrt(v0));
            atth[a1]     = __float2bfloat16(v1);
            attl[a1]     = __float2bfloat16(v1 - bfrt(v1));
            atth[a0 + 8] = __float2bfloat16(v2);
            attl[a0 + 8] = __float2bfloat16(v2 - bfrt(v2));
            atth[a1 + 8] = __float2bfloat16(v3);
            attl[a1 + 8] = __float2bfloat16(v3 - bfrt(v3));
        }
    }
}

// ---------------------------------------------------------------------------
extern "C" void kernel_launch(void* const* d_in, const int* in_sizes, int n_in,
                              void* d_out, int out_size)
{
    const float* x     = (const float*)d_in[0];
    const float* w_qkv = (const float*)d_in[1];
    const float* w_out = (const float*)d_in[2];
    const float* b_out = (const float*)d_in[3];
    float* out = (float*)d_out;

    __nv_bfloat16 *xh, *xl, *wqh, *wql, *woh, *wol, *qkvh, *qkvl, *atth, *attl;
    cudaGetSymbolAddress((void**)&xh,   g_xh);
    cudaGetSymbolAddress((void**)&xl,   g_xl);
    cudaGetSymbolAddress((void**)&wqh,  g_wqh);
    cudaGetSymbolAddress((void**)&wql,  g_wql);
    cudaGetSymbolAddress((void**)&woh,  g_woh);
    cudaGetSymbolAddress((void**)&wol,  g_wol);
    cudaGetSymbolAddress((void**)&qkvh, g_qkvh);
    cudaGetSymbolAddress((void**)&qkvl, g_qkvl);
    cudaGetSymbolAddress((void**)&atth, g_atth);
    cudaGetSymbolAddress((void**)&attl, g_attl);

    // 0) split inputs/weights
    cvt_split<<<(NB * NC * NL / 4) / 256, 256>>>(
        (const float4*)x, (uint2*)xh, (uint2*)xl);
    cvt_splitT<<<(NOQKV * NC) / 256, 256>>>(w_qkv, wqh, wql, NOQKV, NC);
    cvt_splitT<<<(NC * NHID) / 256, 256>>>(w_out, woh, wol, NC, NHID);

    const int gsmem = 3 * GSTG;            // 104448
    const int asmem = 34816 + 2 * ASTG;    // 108544

    // 1) QKV projection
    cudaFuncSetAttribute(gemm_bf16<NOQKV, NC, false, true>,
                         cudaFuncAttributeMaxDynamicSharedMemorySize, gsmem);
    gemm_bf16<NOQKV, NC, false, true>
        <<<dim3(NL / 128, NOQKV / 128, NB), 128, gsmem>>>(
            wqh, wql, xh, xl, nullptr, qkvh, qkvl, nullptr);

    // 2) Attention
    cudaFuncSetAttribute(attn_kernel,
                         cudaFuncAttributeMaxDynamicSharedMemorySize, asmem);
    attn_kernel<<<dim3(NL / 128, NH, NB), 128, asmem>>>(qkvh, qkvl, atth, attl);

    // 3) Output projection + bias
    cudaFuncSetAttribute(gemm_bf16<NC, NHID, true, false>,
                         cudaFuncAttributeMaxDynamicSharedMemorySize, gsmem);
    gemm_bf16<NC, NHID, true, false>
        <<<dim3(NL / 128, NC / 128, NB), 128, gsmem>>>(
            woh, wol, atth, attl, b_out, nullptr, nullptr, out);
}

// round 9
// speedup vs baseline: 4.3804x; 1.0148x over previous
#include <cuda_runtime.h>
#include <cuda_bf16.h>

#define NB    8
#define NC    512
#define NL    2048
#define NH    8
#define ND    64
#define NHID  512
#define NOQKV 1536

// ---------------- device-global scratch (allocation-free) ----------------
__device__ __nv_bfloat16 g_xh[(size_t)NB * NC * NL];
__device__ __nv_bfloat16 g_xl[(size_t)NB * NC * NL];
__device__ __nv_bfloat16 g_wqh[(size_t)NC * NOQKV];    // [c][m] transposed
__device__ __nv_bfloat16 g_wql[(size_t)NC * NOQKV];
__device__ __nv_bfloat16 g_woh[(size_t)NHID * NC];     // [c][m] transposed
__device__ __nv_bfloat16 g_wol[(size_t)NHID * NC];
__device__ __nv_bfloat16 g_qkvh[(size_t)NB * NOQKV * NL];
__device__ __nv_bfloat16 g_qkvl[(size_t)NB * NOQKV * NL];
__device__ __nv_bfloat16 g_atth[(size_t)NB * NHID * NL];
__device__ __nv_bfloat16 g_attl[(size_t)NB * NHID * NL];

__device__ __forceinline__ float ex2(float x) {
    float y; asm("ex2.approx.f32 %0, %1;" : "=f"(y) : "f"(x)); return y;
}
__device__ __forceinline__ unsigned pckbf(float lo, float hi) {
    unsigned r; asm("cvt.rn.bf16x2.f32 %0, %1, %2;" : "=r"(r) : "f"(hi), "f"(lo)); return r;
}
__device__ __forceinline__ float bfrt(float x) {
    float r;
    asm("{.reg .b16 t; cvt.rn.bf16.f32 t, %1; cvt.f32.bf16 %0, t;}" : "=f"(r) : "f"(x));
    return r;
}
__device__ __forceinline__ void cpa16(unsigned s, const void* g) {
    asm volatile("cp.async.cg.shared.global [%0], [%1], 16;" :: "r"(s), "l"(g));
}
#define CPCOMMIT() asm volatile("cp.async.commit_group;")
#define CPWAIT(n)  asm volatile("cp.async.wait_group %0;" :: "n"(n))

#define LDSMX4(R0,R1,R2,R3,A) \
    asm volatile("ldmatrix.sync.aligned.m8n8.x4.shared.b16 {%0,%1,%2,%3}, [%4];" \
        : "=r"(R0),"=r"(R1),"=r"(R2),"=r"(R3) : "r"(A))
#define LDSMX4T(R0,R1,R2,R3,A) \
    asm volatile("ldmatrix.sync.aligned.m8n8.x4.trans.shared.b16 {%0,%1,%2,%3}, [%4];" \
        : "=r"(R0),"=r"(R1),"=r"(R2),"=r"(R3) : "r"(A))
// NOTE: NOT volatile — register-only op; lets ptxas interleave independent MMAs
#define MMABF(C,A0,A1,A2,A3,B0,B1) \
    asm("mma.sync.aligned.m16n8k16.row.col.f32.bf16.bf16.f32 " \
        "{%0,%1,%2,%3},{%4,%5,%6,%7},{%8,%9},{%0,%1,%2,%3};" \
        : "+f"(C[0]),"+f"(C[1]),"+f"(C[2]),"+f"(C[3]) \
        : "r"(A0),"r"(A1),"r"(A2),"r"(A3),"r"(B0),"r"(B1))

// ---------------------------------------------------------------------------
// fp32 -> bf16 hi/lo split passes
// ---------------------------------------------------------------------------
__global__ void cvt_split(const float4* __restrict__ src,
                          uint2* __restrict__ h, uint2* __restrict__ l)
{
    int i = blockIdx.x * blockDim.x + threadIdx.x;
    float4 f = src[i];
    uint2 hv, lv;
    hv.x = pckbf(f.x, f.y);
    hv.y = pckbf(f.z, f.w);
    lv.x = pckbf(f.x - bfrt(f.x), f.y - bfrt(f.y));
    lv.y = pckbf(f.z - bfrt(f.z), f.w - bfrt(f.w));
    h[i] = hv; l[i] = lv;
}

__global__ void cvt_splitT(const float* __restrict__ w,
                           __nv_bfloat16* __restrict__ ht,
                           __nv_bfloat16* __restrict__ lt, int M, int C)
{
    int idx = blockIdx.x * blockDim.x + threadIdx.x;
    int m = idx / C, c = idx % C;
    float v = w[idx];
    float hi = bfrt(v);
    ht[(size_t)c * M + m] = __float2bfloat16(hi);
    lt[(size_t)c * M + m] = __float2bfloat16(v - hi);
}

// ---------------------------------------------------------------------------
// bf16 split-MMA GEMM, 3-stage cp.async pipeline.
// Block 128x128, ktile 32, 128 threads = 4 warps in 2x2 grid, 64x64 per warp.
// Split MMAs issued in 3 passes (hi*hi, hi*lo, lo*hi) -> 8-MMA reuse distance.
// ---------------------------------------------------------------------------
#define GSTG 34816   // bytes per stage: 4 arrays x 32 x 136 x 2B

template<int M, int K, bool HAS_BIAS, bool SPLIT_OUT>
__global__ __launch_bounds__(128) void gemm_bf16(
    const __nv_bfloat16* __restrict__ Ah_g, const __nv_bfloat16* __restrict__ Al_g,
    const __nv_bfloat16* __restrict__ Bh_g, const __nv_bfloat16* __restrict__ Bl_g,
    const float* __restrict__ bias,
    __nv_bfloat16* __restrict__ Yh, __nv_bfloat16* __restrict__ Yl,
    float* __restrict__ Yf)
{
    extern __shared__ __align__(16) unsigned char smg[];
    const int NT = K / 32;

    const int b  = blockIdx.z;
    const int m0 = blockIdx.y * 128;
    const int n0 = blockIdx.x * 128;

    const int tid  = threadIdx.x;
    const int lane = tid & 31;
    const int warp = tid >> 5;      // 0..3
    const int wm   = warp >> 1;     // m offset wm*64
    const int wn   = warp & 1;      // n offset wn*64

    unsigned sb = (unsigned)__cvta_generic_to_shared(smg);

    const unsigned offA = ((((lane >> 4) & 1) * 8 + (lane & 7)) * 272)
                        + (wm * 64 + ((lane >> 3) & 1) * 8) * 2;
    const unsigned offB = ((((lane >> 3) & 1) * 8 + (lane & 7)) * 272)
                        + (wn * 64 + ((lane >> 4) & 1) * 8) * 2;

    float acc[4][8][4];
    #pragma unroll
    for (int i = 0; i < 4; i++)
        #pragma unroll
        for (int j = 0; j < 8; j++)
            #pragma unroll
            for (int t = 0; t < 4; t++) acc[i][j][t] = 0.0f;

    auto issue = [&](int kt, int st) {
        unsigned base = sb + st * GSTG;
        int k0 = kt * 32;
        #pragma unroll
        for (int p = 0; p < 4; p++) {
            int q   = tid + p * 128;
            int row = q >> 4;
            int c8  = (q & 15) * 8;
            size_t ga = (size_t)(k0 + row) * M + m0 + c8;
            size_t gb = ((size_t)b * K + k0 + row) * NL + n0 + c8;
            unsigned so = row * 272 + c8 * 2;
            cpa16(base + so,          Ah_g + ga);
            cpa16(base + 8704 + so,   Al_g + ga);
            cpa16(base + 17408 + so,  Bh_g + gb);
            cpa16(base + 26112 + so,  Bl_g + gb);
        }
    };

    issue(0, 0); CPCOMMIT();
    issue(1, 1); CPCOMMIT();

    for (int kt = 0; kt < NT; kt++) {
        CPWAIT(1);
        __syncthreads();
        if (kt + 2 < NT) issue(kt + 2, (kt + 2) % 3);
        CPCOMMIT();

        unsigned base = sb + (kt % 3) * GSTG;
        const unsigned SAH = base, SAL = base + 8704,
                       SBH = base + 17408, SBL = base + 26112;

        #pragma unroll
        for (int kc = 0; kc < 2; kc++) {
            unsigned kb = kc * 16 * 272;
            unsigned bh[4][4], bl[4][4];
            #pragma unroll
            for (int ng = 0; ng < 4; ng++) {
                LDSMX4T(bh[ng][0], bh[ng][1], bh[ng][2], bh[ng][3],
                        SBH + offB + kb + ng * 32);
                LDSMX4T(bl[ng][0], bl[ng][1], bl[ng][2], bl[ng][3],
                        SBL + offB + kb + ng * 32);
            }
            #pragma unroll
            for (int mf = 0; mf < 4; mf++) {
                unsigned ah0,ah1,ah2,ah3, al0,al1,al2,al3;
                LDSMX4T(ah0,ah1,ah2,ah3, SAH + offA + kb + mf * 32);
                LDSMX4T(al0,al1,al2,al3, SAL + offA + kb + mf * 32);
                // pass 1: hi*hi across all 8 accumulators
                #pragma unroll
                for (int ng = 0; ng < 4; ng++) {
                    MMABF(acc[mf][2*ng],   ah0,ah1,ah2,ah3, bh[ng][0],bh[ng][1]);
                    MMABF(acc[mf][2*ng+1], ah0,ah1,ah2,ah3, bh[ng][2],bh[ng][3]);
                }
                // pass 2: hi*lo
                #pragma unroll
                for (int ng = 0; ng < 4; ng++) {
                    MMABF(acc[mf][2*ng],   ah0,ah1,ah2,ah3, bl[ng][0],bl[ng][1]);
                    MMABF(acc[mf][2*ng+1], ah0,ah1,ah2,ah3, bl[ng][2],bl[ng][3]);
                }
                // pass 3: lo*hi
                #pragma unroll
                for (int ng = 0; ng < 4; ng++) {
                    MMABF(acc[mf][2*ng],   al0,al1,al2,al3, bh[ng][0],bh[ng][1]);
                    MMABF(acc[mf][2*ng+1], al0,al1,al2,al3, bh[ng][2],bh[ng][3]);
                }
            }
        }
    }

    // ---- epilogue ----
    const int r0 = lane >> 2;
    const int cp = (lane & 3) * 2;
    #pragma unroll
    for (int mf = 0; mf < 4; mf++) {
        int ml = m0 + wm * 64 + mf * 16 + r0;
        float bv0 = 0.0f, bv1 = 0.0f;
        if (HAS_BIAS) { bv0 = bias[ml]; bv1 = bias[ml + 8]; }
        #pragma unroll
        for (int g = 0; g < 8; g++) {
            int n = n0 + wn * 64 + (g >> 1) * 16 + (g & 1) * 8 + cp;
            float* c = acc[mf][g];
            size_t a0 = ((size_t)b * M + ml) * NL + n;
            size_t a1 = a0 + (size_t)8 * NL;
            if (SPLIT_OUT) {
                *(unsigned*)(Yh + a0) = pckbf(c[0], c[1]);
                *(unsigned*)(Yl + a0) = pckbf(c[0] - bfrt(c[0]), c[1] - bfrt(c[1]));
                *(unsigned*)(Yh + a1) = pckbf(c[2], c[3]);
                *(unsigned*)(Yl + a1) = pckbf(c[2] - bfrt(c[2]), c[3] - bfrt(c[3]));
            } else {
                *(float2*)(Yf + a0) = make_float2(c[0] + bv0, c[1] + bv0);
                *(float2*)(Yf + a1) = make_float2(c[2] + bv1, c[3] + bv1);
            }
        }
    }
}

// ---------------------------------------------------------------------------
// Flash attention: BM=128 queries, 4 warps x m32 rows each, BN=64 keys,
// 2-stage cp.async K/V pipeline, split MMAs in 3 passes.
// ---------------------------------------------------------------------------
#define ASTG 36864

__global__ __launch_bounds__(128) void attn_kernel(
    const __nv_bfloat16* __restrict__ qkvh, const __nv_bfloat16* __restrict__ qkvl,
    __nv_bfloat16* __restrict__ atth, __nv_bfloat16* __restrict__ attl)
{
    extern __shared__ __align__(16) unsigned char sma[];

    const int tid  = threadIdx.x;
    const int lane = tid & 31;
    const int warp = tid >> 5;     // 0..3, rows warp*32..warp*32+31
    const int i0 = blockIdx.x * 128;
    const int h  = blockIdx.y;
    const int b  = blockIdx.z;

    const size_t base = ((size_t)b * NOQKV + h * ND) * NL;
    const __nv_bfloat16* qph = qkvh + base;
    const __nv_bfloat16* qpl = qkvl + base;
    const __nv_bfloat16* kph = qph + (size_t)NHID * NL;
    const __nv_bfloat16* kpl = qpl + (size_t)NHID * NL;
    const __nv_bfloat16* vph = qph + (size_t)2 * NHID * NL;
    const __nv_bfloat16* vpl = qpl + (size_t)2 * NHID * NL;

    unsigned sb = (unsigned)__cvta_generic_to_shared(sma);
    const unsigned QH = sb, QL = sb + 17408, KV0 = sb + 34816;

    const unsigned offQ = (((lane >> 4) & 1) * 8 + (lane & 7)) * 272
                        + (warp * 32 + ((lane >> 3) & 1) * 8) * 2;
    const unsigned offK = (((lane >> 3) & 1) * 8 + (lane & 7)) * 144
                        + (((lane >> 4) & 1) * 8) * 2;
    const unsigned offV = (((lane >> 4) & 1) * 8 + (lane & 7)) * 144
                        + (((lane >> 3) & 1) * 8) * 2;

    const float SC = 0.125f * 1.44269504f;

    auto issueKV = [&](int j0, int st) {
        unsigned kb = KV0 + st * ASTG;
        #pragma unroll
        for (int p = 0; p < 4; p++) {
            int q   = tid + p * 128;
            int row = q >> 3;
            int col = (q & 7) * 8;
            unsigned so = row * 144 + col * 2;
            size_t g = (size_t)row * NL + j0 + col;
            cpa16(kb + so,          kph + g);
            cpa16(kb + 9216 + so,   kpl + g);
            cpa16(kb + 18432 + so,  vph + g);
            cpa16(kb + 27648 + so,  vpl + g);
        }
    };

    {
        #pragma unroll
        for (int p = 0; p < 8; p++) {
            int q = tid + p * 128;
            int r = q >> 4, c16 = (q & 15) * 8;
            unsigned so = r * 272 + c16 * 2;
            size_t g = (size_t)r * NL + i0 + c16;
            cpa16(QH + so, qph + g);
            cpa16(QL + so, qpl + g);
        }
        issueKV(0, 0);
        CPCOMMIT();
    }

    float o[2][8][4];
    float mm[2][2], ll[2][2];
    #pragma unroll
    for (int mb = 0; mb < 2; mb++) {
        mm[mb][0] = -1e30f; mm[mb][1] = -1e30f;
        ll[mb][0] = 0.0f;   ll[mb][1] = 0.0f;
        #pragma unroll
        for (int t = 0; t < 8; t++)
            #pragma unroll
            for (int c = 0; c < 4; c++) o[mb][t][c] = 0.0f;
    }

    for (int jt = 0; jt < 32; jt++) {
        if (jt + 1 < 32) issueKV((jt + 1) * 64, (jt + 1) & 1);
        CPCOMMIT();
        CPWAIT(1);
        __syncthreads();

        unsigned kb = KV0 + (jt & 1) * ASTG;
        const unsigned KH = kb, KL = kb + 9216, VH = kb + 18432, VL = kb + 27648;

        // ---- S = Q K^T : m32 x n64 per warp, 3-pass split ----
        float s[2][8][4];
        #pragma unroll
        for (int mb = 0; mb < 2; mb++)
            #pragma unroll
            for (int t = 0; t < 8; t++)
                #pragma unroll
                for (int c = 0; c < 4; c++) s[mb][t][c] = 0.0f;

        #pragma unroll
        for (int kc = 0; kc < 4; kc++) {
            unsigned kcq = kc * 16 * 272;
            unsigned kck = kc * 16 * 144;
            unsigned qa[2][4], qe[2][4];
            LDSMX4T(qa[0][0],qa[0][1],qa[0][2],qa[0][3], QH + offQ + kcq);
            LDSMX4T(qa[1][0],qa[1][1],qa[1][2],qa[1][3], QH + offQ + kcq + 32);
            LDSMX4T(qe[0][0],qe[0][1],qe[0][2],qe[0][3], QL + offQ + kcq);
            LDSMX4T(qe[1][0],qe[1][1],qe[1][2],qe[1][3], QL + offQ + kcq + 32);
            #pragma unroll
            for (int p = 0; p < 4; p++) {
                unsigned nb = p * 32;
                unsigned h0,h1,h2,h3, e0,e1,e2,e3;
                LDSMX4T(h0,h1,h2,h3, KH + offK + kck + nb);
                LDSMX4T(e0,e1,e2,e3, KL + offK + kck + nb);
                // pass 1: qhi*khi (4 independent accs)
                #pragma unroll
                for (int mb = 0; mb < 2; mb++) {
                    MMABF(s[mb][2*p],   qa[mb][0],qa[mb][1],qa[mb][2],qa[mb][3], h0,h1);
                    MMABF(s[mb][2*p+1], qa[mb][0],qa[mb][1],qa[mb][2],qa[mb][3], h2,h3);
                }
                // pass 2: qhi*klo
                #pragma unroll
                for (int mb = 0; mb < 2; mb++) {
                    MMABF(s[mb][2*p],   qa[mb][0],qa[mb][1],qa[mb][2],qa[mb][3], e0,e1);
                    MMABF(s[mb][2*p+1], qa[mb][0],qa[mb][1],qa[mb][2],qa[mb][3], e2,e3);
                }
                // pass 3: qlo*khi
                #pragma unroll
                for (int mb = 0; mb < 2; mb++) {
                    MMABF(s[mb][2*p],   qe[mb][0],qe[mb][1],qe[mb][2],qe[mb][3], h0,h1);
                    MMABF(s[mb][2*p+1], qe[mb][0],qe[mb][1],qe[mb][2],qe[mb][3], h2,h3);
                }
            }
        }

        // ---- online softmax + P fragments per mb ----
        unsigned pah[2][4][4], pal[2][4][4];
        #pragma unroll
        for (int mb = 0; mb < 2; mb++) {
            float mx0 = -1e30f, mx1 = -1e30f;
            #pragma unroll
            for (int t = 0; t < 8; t++) {
                s[mb][t][0] *= SC; s[mb][t][1] *= SC;
                s[mb][t][2] *= SC; s[mb][t][3] *= SC;
                mx0 = fmaxf(mx0, fmaxf(s[mb][t][0], s[mb][t][1]));
                mx1 = fmaxf(mx1, fmaxf(s[mb][t][2], s[mb][t][3]));
            }
            mx0 = fmaxf(mx0, __shfl_xor_sync(0xffffffffu, mx0, 1));
            mx0 = fmaxf(mx0, __shfl_xor_sync(0xffffffffu, mx0, 2));
            mx1 = fmaxf(mx1, __shfl_xor_sync(0xffffffffu, mx1, 1));
            mx1 = fmaxf(mx1, __shfl_xor_sync(0xffffffffu, mx1, 2));
            float mn0 = fmaxf(mm[mb][0], mx0), mn1 = fmaxf(mm[mb][1], mx1);
            float c0 = ex2(mm[mb][0] - mn0),   c1 = ex2(mm[mb][1] - mn1);
            mm[mb][0] = mn0; mm[mb][1] = mn1;

            float rs0 = 0.0f, rs1 = 0.0f;
            #pragma unroll
            for (int t = 0; t < 8; t++) {
                s[mb][t][0] = ex2(s[mb][t][0] - mn0);
                s[mb][t][1] = ex2(s[mb][t][1] - mn0);
                s[mb][t][2] = ex2(s[mb][t][2] - mn1);
                s[mb][t][3] = ex2(s[mb][t][3] - mn1);
                rs0 += s[mb][t][0] + s[mb][t][1];
                rs1 += s[mb][t][2] + s[mb][t][3];
            }
            ll[mb][0] = ll[mb][0] * c0 + rs0;
            ll[mb][1] = ll[mb][1] * c1 + rs1;
            #pragma unroll
            for (int t = 0; t < 8; t++) {
                o[mb][t][0] *= c0; o[mb][t][1] *= c0;
                o[mb][t][2] *= c1; o[mb][t][3] *= c1;
            }
            #pragma unroll
            for (int c = 0; c < 4; c++) {
                int A = 2 * c, B = 2 * c + 1;
                pah[mb][c][0] = pckbf(s[mb][A][0], s[mb][A][1]);
                pah[mb][c][1] = pckbf(s[mb][A][2], s[mb][A][3]);
                pah[mb][c][2] = pckbf(s[mb][B][0], s[mb][B][1]);
                pah[mb][c][3] = pckbf(s[mb][B][2], s[mb][B][3]);
                pal[mb][c][0] = pckbf(s[mb][A][0]-bfrt(s[mb][A][0]), s[mb][A][1]-bfrt(s[mb][A][1]));
                pal[mb][c][1] = pckbf(s[mb][A][2]-bfrt(s[mb][A][2]), s[mb][A][3]-bfrt(s[mb][A][3]));
                pal[mb][c][2] = pckbf(s[mb][B][0]-bfrt(s[mb][B][0]), s[mb][B][1]-bfrt(s[mb][B][1]));
                pal[mb][c][3] = pckbf(s[mb][B][2]-bfrt(s[mb][B][2]), s[mb][B][3]-bfrt(s[mb][B][3]));
            }
        }

        // ---- O += P V : shared V fragments, 3-pass split ----
        #pragma unroll
        for (int c = 0; c < 4; c++) {
            unsigned jb = c * 32;
            #pragma unroll
            for (int p = 0; p < 4; p++) {
                unsigned db = p * 2304;
                unsigned h0,h1,h2,h3, e0,e1,e2,e3;
                LDSMX4(h0,h1,h2,h3, VH + offV + db + jb);
                LDSMX4(e0,e1,e2,e3, VL + offV + db + jb);
                #pragma unroll
                for (int mb = 0; mb < 2; mb++) {
                    MMABF(o[mb][2*p],   pah[mb][c][0],pah[mb][c][1],pah[mb][c][2],pah[mb][c][3], h0,h1);
                    MMABF(o[mb][2*p+1], pah[mb][c][0],pah[mb][c][1],pah[mb][c][2],pah[mb][c][3], h2,h3);
                }
                #pragma unroll
                for (int mb = 0; mb < 2; mb++) {
                    MMABF(o[mb][2*p],   pah[mb][c][0],pah[mb][c][1],pah[mb][c][2],pah[mb][c][3], e0,e1);
                    MMABF(o[mb][2*p+1], pah[mb][c][0],pah[mb][c][1],pah[mb][c][2],pah[mb][c][3], e2,e3);
                }
                #pragma unroll
                for (int mb = 0; mb < 2; mb++) {
                    MMABF(o[mb][2*p],   pal[mb][c][0],pal[mb][c][1],pal[mb][c][2],pal[mb][c][3], h0,h1);
                    MMABF(o[mb][2*p+1], pal[mb][c][0],pal[mb][c][1],pal[mb][c][2],pal[mb][c][3], h2,h3);
                }
            }
        }
        __syncthreads();
    }

    // ---- finalize ----
    const size_t ob = ((size_t)b * NHID + h * ND) * NL;
    #pragma unroll
    for (int mb = 0; mb < 2; mb++) {
        float l0 = ll[mb][0], l1 = ll[mb][1];
        l0 += __shfl_xor_sync(0xffffffffu, l0, 1);
        l0 += __shfl_xor_sync(0xffffffffu, l0, 2);
        l1 += __shfl_xor_sync(0xffffffffu, l1, 1);
        l1 += __shfl_xor_sync(0xffffffffu, l1, 2);
        float inv0 = __fdividef(1.0f, l0);
        float inv1 = __fdividef(1.0f, l1);

        int ig = i0 + warp * 32 + mb * 16 + (lane >> 2);
        #pragma unroll
        for (int dt = 0; dt < 8; dt++) {
            int d = dt * 8 + (lane & 3) * 2;
            float v0 = o[mb][dt][0] * inv0, v1 = o[mb][dt][1] * inv0;
            float v2 = o[mb][dt][2] * inv1, v3 = o[mb][dt][3] * inv1;
            size_t a0 = ob + (size_t)d * NL + ig;
            size_t a1 = ob + (size_t)(d + 1) * NL + ig;
            atth[a0]     = __float2bfloat16(v0);
            attl[a0]     = __float2bfloat16(v0 - bfrt(v0));
            atth[a1]     = __float2bfloat16(v1);
            attl[a1]     = __float2bfloat16(v1 - bfrt(v1));
            atth[a0 + 8] = __float2bfloat16(v2);
            attl[a0 + 8] = __float2bfloat16(v2 - bfrt(v2));
            atth[a1 + 8] = __float2bfloat16(v3);
            attl[a1 + 8] = __float2bfloat16(v3 - bfrt(v3));
        }
    }
}

// ---------------------------------------------------------------------------
extern "C" void kernel_launch(void* const* d_in, const int* in_sizes, int n_in,
                              void* d_out, int out_size)
{
    const float* x     = (const float*)d_in[0];
    const float* w_qkv = (const float*)d_in[1];
    const float* w_out = (const float*)d_in[2];
    const float* b_out = (const float*)d_in[3];
    float* out = (float*)d_out;

    __nv_bfloat16 *xh, *xl, *wqh, *wql, *woh, *wol, *qkvh, *qkvl, *atth, *attl;
    cudaGetSymbolAddress((void**)&xh,   g_xh);
    cudaGetSymbolAddress((void**)&xl,   g_xl);
    cudaGetSymbolAddress((void**)&wqh,  g_wqh);
    cudaGetSymbolAddress((void**)&wql,  g_wql);
    cudaGetSymbolAddress((void**)&woh,  g_woh);
    cudaGetSymbolAddress((void**)&wol,  g_wol);
    cudaGetSymbolAddress((void**)&qkvh, g_qkvh);
    cudaGetSymbolAddress((void**)&qkvl, g_qkvl);
    cudaGetSymbolAddress((void**)&atth, g_atth);
    cudaGetSymbolAddress((void**)&attl, g_attl);

    // 0) split inputs/weights
    cvt_split<<<(NB * NC * NL / 4) / 256, 256>>>(
        (const float4*)x, (uint2*)xh, (uint2*)xl);
    cvt_splitT<<<(NOQKV * NC) / 256, 256>>>(w_qkv, wqh, wql, NOQKV, NC);
    cvt_splitT<<<(NC * NHID) / 256, 256>>>(w_out, woh, wol, NC, NHID);

    const int gsmem = 3 * GSTG;            // 104448
    const int asmem = 34816 + 2 * ASTG;    // 108544

    // 1) QKV projection
    cudaFuncSetAttribute(gemm_bf16<NOQKV, NC, false, true>,
                         cudaFuncAttributeMaxDynamicSharedMemorySize, gsmem);
    gemm_bf16<NOQKV, NC, false, true>
        <<<dim3(NL / 128, NOQKV / 128, NB), 128, gsmem>>>(
            wqh, wql, xh, xl, nullptr, qkvh, qkvl, nullptr);

    // 2) Attention
    cudaFuncSetAttribute(attn_kernel,
                         cudaFuncAttributeMaxDynamicSharedMemorySize, asmem);
    attn_kernel<<<dim3(NL / 128, NH, NB), 128, asmem>>>(qkvh, qkvl, atth, attl);

    // 3) Output projection + bias
    cudaFuncSetAttribute(gemm_bf16<NC, NHID, true, false>,
                         cudaFuncAttributeMaxDynamicSharedMemorySize, gsmem);
    gemm_bf16<NC, NHID, true, false>
        <<<dim3(NL / 128, NC / 128, NB), 128, gsmem>>>(
            woh, wol, atth, attl, b_out, nullptr, nullptr, out);
}